// round 10
// baseline (speedup 1.0000x reference)
#include <cuda_runtime.h>
#include <cuda_fp16.h>
#include <cstdint>

#define N_NODES 40000
#define N_EDGES 640000
#define C_DIM   128
#define OUT_CH  64
#define BUCKET  64
#define NBLK    313          // ceil(40000/128)
#define SLAB    16384        // words per 128-row A-frag slab (128x128)

// ---------------- device scratch (no allocations allowed) ----------------
__device__ __half g_xH[N_NODES * C_DIM];    // fp16 copy of x for gather
__device__ __half g_h1H[N_NODES * C_DIM];   // fp16 copy of h1 for gather
__device__ float g_meanF[NBLK * SLAB];
__device__ float g_xF[NBLK * SLAB];
__device__ float g_h1F[NBLK * SLAB];
__device__ float g_h2F[NBLK * SLAB];
__device__ float g_w1lF[SLAB], g_w1rF[SLAB], g_w2lF[SLAB], g_w2rF[SLAB], g_headBF[SLAB];
__device__ int   g_cursor[N_NODES];   // zero-initialized; self-restored each run
__device__ int   g_csr[N_NODES * BUCKET];
__device__ int   g_is64;

// ---------------- helpers ----------------
__device__ __forceinline__ uint32_t f2tf(float v) {
    uint32_t r; asm("cvt.rna.tf32.f32 %0, %1;" : "=r"(r) : "f"(v)); return r;
}
__device__ __forceinline__ uint32_t smem_u32(const void* p) {
    uint32_t a;
    asm("{ .reg .u64 t; cvta.to.shared.u64 t, %1; cvt.u32.u64 %0, t; }" : "=r"(a) : "l"(p));
    return a;
}
__device__ __forceinline__ void cp16(uint32_t dst, const void* src) {
    asm volatile("cp.async.ca.shared.global [%0], [%1], 16;" :: "r"(dst), "l"(src));
}
#define CP_COMMIT() asm volatile("cp.async.commit_group;" ::: "memory")
#define CP_WAIT1()  asm volatile("cp.async.wait_group 1;" ::: "memory")
#define CP_WAIT0()  asm volatile("cp.async.wait_group 0;" ::: "memory")

__device__ __forceinline__ uint2 pack_half4(float a, float b, float c, float d) {
    __half2 h01 = __floats2half2_rn(a, b);
    __half2 h23 = __floats2half2_rn(c, d);
    uint2 p;
    p.x = *(uint32_t*)&h01;
    p.y = *(uint32_t*)&h23;
    return p;
}

__device__ __forceinline__ void mma_tf32(float& d0, float& d1, float& d2, float& d3,
                                         uint32_t a0, uint32_t a1, uint32_t a2, uint32_t a3,
                                         uint32_t b0, uint32_t b1) {
    asm volatile(
        "mma.sync.aligned.m16n8k8.row.col.f32.tf32.tf32.f32 "
        "{%0,%1,%2,%3}, {%4,%5,%6,%7}, {%8,%9}, {%0,%1,%2,%3};"
        : "+f"(d0), "+f"(d1), "+f"(d2), "+f"(d3)
        : "r"(a0), "r"(a1), "r"(a2), "r"(a3), "r"(b0), "r"(b1));
}

// mma over one staged 128x128x32 chunk; warp tile 64 nodes x 32 outs
// A chunk layout: [k8=4][m_tile=8][reg=4][lane=32]; B: [k8=4][n_tile=16][reg=2][lane=32]
__device__ __forceinline__ void mma_chunk(const uint32_t* sA, const uint32_t* sB,
                                          float acc[4][4][4], int wm, int wn, int lid) {
#pragma unroll
    for (int k8 = 0; k8 < 4; k8++) {
        uint32_t a[4][4], b[4][2];
#pragma unroll
        for (int i = 0; i < 4; i++) {
            uint32_t base = ((k8 * 8 + (wm * 4 + i)) * 4) * 32 + lid;
            a[i][0] = sA[base];      a[i][1] = sA[base + 32];
            a[i][2] = sA[base + 64]; a[i][3] = sA[base + 96];
        }
#pragma unroll
        for (int j = 0; j < 4; j++) {
            uint32_t base = ((k8 * 16 + (wn * 4 + j)) * 2) * 32 + lid;
            b[j][0] = sB[base]; b[j][1] = sB[base + 32];
        }
#pragma unroll
        for (int i = 0; i < 4; i++)
#pragma unroll
            for (int j = 0; j < 4; j++)
                mma_tf32(acc[i][j][0], acc[i][j][1], acc[i][j][2], acc[i][j][3],
                         a[i][0], a[i][1], a[i][2], a[i][3], b[j][0], b[j][1]);
    }
}

// ---------------- index dtype detection ----------------
__global__ void detect_kernel(const int* ei) {
    if (blockIdx.x == 0 && threadIdx.x == 0) {
        bool is64 = true;
        for (int i = 0; i < 64; i++) {
            int lo = ei[2 * i];
            int hi = ei[2 * i + 1];
            if (hi != 0 || (unsigned)lo >= (unsigned)N_NODES) { is64 = false; break; }
        }
        g_is64 = is64 ? 1 : 0;
    }
}
__device__ __forceinline__ int load_idx(const void* ei, int pos, int is64) {
    if (is64) return (int)((const long long*)ei)[pos];
    return ((const int*)ei)[pos];
}

// ---------------- bucketed CSR build (cursor zeroed by prior run / init) --------
__global__ void fill_kernel(const void* __restrict__ ei, int* __restrict__ cursor,
                            int* __restrict__ csr) {
    int e = blockIdx.x * blockDim.x + threadIdx.x;
    if (e >= N_EDGES) return;
    int is64 = g_is64;
    int src = load_idx(ei, e, is64);
    int dst = load_idx(ei, N_EDGES + e, is64);
    int pos = atomicAdd(&cursor[dst], 1);
    if (pos < BUCKET) csr[dst * BUCKET + pos] = src;
}

// ---------------- weight prep: row-major fp32 -> B-frag tf32 ----------------
__global__ void prepw_kernel(const float* __restrict__ w1l, const float* __restrict__ w1r,
                             const float* __restrict__ w2l, const float* __restrict__ w2r,
                             const float* __restrict__ wa, const float* __restrict__ wc,
                             float* __restrict__ w1lF, float* __restrict__ w1rF,
                             float* __restrict__ w2lF, float* __restrict__ w2rF,
                             float* __restrict__ headBF) {
    int gid = blockIdx.x * blockDim.x + threadIdx.x;   // 0..20479
    int m = gid >> 12, g = gid & 4095;
    int w = g * 4;
    int lane = w & 31, reg = (w >> 5) & 1, ntile = (w >> 6) & 15, k8 = w >> 10;
    int n = ntile * 8 + (lane >> 2);
    int k = k8 * 8 + reg * 4;
    float4 v = make_float4(0.f, 0.f, 0.f, 0.f);
    float* dst;
    switch (m) {
        case 0: v = __ldg((const float4*)(w1l + (size_t)n * C_DIM + k)); dst = w1lF; break;
        case 1: v = __ldg((const float4*)(w1r + (size_t)n * C_DIM + k)); dst = w1rF; break;
        case 2: v = __ldg((const float4*)(w2l + (size_t)n * C_DIM + k)); dst = w2lF; break;
        case 3: v = __ldg((const float4*)(w2r + (size_t)n * C_DIM + k)); dst = w2rF; break;
        default:
            if (n < 64)       v = __ldg((const float4*)(wa + (size_t)n * C_DIM + k));
            else if (n == 64) v = __ldg((const float4*)(wc + k));
            dst = headBF; break;
    }
    *(uint4*)(dst + w) = make_uint4(f2tf(v.x), f2tf(v.y), f2tf(v.z), f2tf(v.w));
}

// ---------------- A converter: one 128x32 chunk per block (grid = NBLK*4) ----------
// Also emits the fp16 copy (xH) for the gather kernels.
__global__ __launch_bounds__(256) void convertA_kernel(const float* __restrict__ src,
                                                       float* __restrict__ dstF,
                                                       __half* __restrict__ dstH) {
    __shared__ __align__(16) float s[128][36];
    const int t = threadIdx.x;
    const int bm = blockIdx.x >> 2;
    const int ch = blockIdx.x & 3;
    const int node0 = bm * 128;
    float* slab = dstF + (size_t)bm * SLAB;
#pragma unroll
    for (int i = 0; i < 4; i++) {
        int idx = t + i * 256;
        int row = idx >> 3, k4 = (idx & 7) * 4;
        int node = node0 + row;
        bool valid = (node < N_NODES);
        if (!valid) node = N_NODES - 1;
        float4 v = __ldg((const float4*)(src + (size_t)node * C_DIM + ch * 32 + k4));
        *(float4*)&s[row][k4] = v;
        if (valid)
            *(uint2*)(dstH + (size_t)node * C_DIM + ch * 32 + k4) =
                pack_half4(v.x, v.y, v.z, v.w);
    }
    __syncthreads();
#pragma unroll
    for (int i = 0; i < 4; i++) {
        int w = (t + i * 256) * 4;   // word index within 4096-word chunk
        int lane = w & 31, reg = (w >> 5) & 3, tile = (w >> 7) & 7, k8 = w >> 10;
        int row = tile * 16 + (reg & 1) * 8 + (lane >> 2);
        int kb = k8 * 8 + ((reg >> 1) & 1) * 4;
        float4 v = *(const float4*)&s[row][kb];
        *(uint4*)(slab + ch * 4096 + w) =
            make_uint4(f2tf(v.x), f2tf(v.y), f2tf(v.z), f2tf(v.w));
    }
}

// ---------------- mean aggregation: warp per node, fp16 sources, fp32 accum ----
// MLP=4 (four independent row loads in flight). Optionally restores cursor=0.
__global__ __launch_bounds__(256) void gather_kernel(int* __restrict__ cursor,
                                                     const int* __restrict__ csr,
                                                     const __half* __restrict__ xh,
                                                     float* __restrict__ meanF,
                                                     int zero_cursor) {
    int gt = blockIdx.x * blockDim.x + threadIdx.x;
    int n = gt >> 5;
    if (n >= N_NODES) return;
    int lane = gt & 31;
    int deg = __ldg(&cursor[n]);
    if (zero_cursor && lane == 0) cursor[n] = 0;   // restore for next replay's fill
    int e = (deg < BUCKET) ? deg : BUCKET;
    const int* bkt = csr + n * BUCKET;
    float4 acc = make_float4(0.f, 0.f, 0.f, 0.f);
    int i = 0;
    for (; i + 4 <= e; i += 4) {
        int s0 = __ldg(&bkt[i + 0]);
        int s1 = __ldg(&bkt[i + 1]);
        int s2 = __ldg(&bkt[i + 2]);
        int s3 = __ldg(&bkt[i + 3]);
        uint2 u0 = __ldg((const uint2*)(xh + (size_t)s0 * C_DIM) + lane);
        uint2 u1 = __ldg((const uint2*)(xh + (size_t)s1 * C_DIM) + lane);
        uint2 u2 = __ldg((const uint2*)(xh + (size_t)s2 * C_DIM) + lane);
        uint2 u3 = __ldg((const uint2*)(xh + (size_t)s3 * C_DIM) + lane);
        float2 a0 = __half22float2(*(__half2*)&u0.x), b0 = __half22float2(*(__half2*)&u0.y);
        float2 a1 = __half22float2(*(__half2*)&u1.x), b1 = __half22float2(*(__half2*)&u1.y);
        float2 a2 = __half22float2(*(__half2*)&u2.x), b2 = __half22float2(*(__half2*)&u2.y);
        float2 a3 = __half22float2(*(__half2*)&u3.x), b3 = __half22float2(*(__half2*)&u3.y);
        acc.x += a0.x + a1.x + a2.x + a3.x;
        acc.y += a0.y + a1.y + a2.y + a3.y;
        acc.z += b0.x + b1.x + b2.x + b3.x;
        acc.w += b0.y + b1.y + b2.y + b3.y;
    }
    for (; i < e; i++) {
        int s0 = __ldg(&bkt[i]);
        uint2 u0 = __ldg((const uint2*)(xh + (size_t)s0 * C_DIM) + lane);
        float2 a0 = __half22float2(*(__half2*)&u0.x), b0 = __half22float2(*(__half2*)&u0.y);
        acc.x += a0.x; acc.y += a0.y; acc.z += b0.x; acc.w += b0.y;
    }
    float inv = 1.0f / fmaxf((float)deg, 1.0f);
    // frag write: lane holds k = 4*lane..4*lane+3 for row r = n&127
    int bm = n >> 7, r = n & 127;
    int k8 = lane >> 1;
    int reg = ((r >> 3) & 1) | ((lane & 1) << 1);
    int tile = (r >> 4) & 7;
    size_t base = (size_t)bm * SLAB + (((k8 * 8 + tile) * 4 + reg) * 32) + ((r & 7) * 4);
    *(uint4*)(meanF + base) = make_uint4(f2tf(acc.x * inv), f2tf(acc.y * inv),
                                         f2tf(acc.z * inv), f2tf(acc.w * inv));
}

// ---------------- pipelined tf32 SAGE GEMM + fused epilogue conversion ----------
__global__ __launch_bounds__(256, 2) void sage_pipe_kernel(
    const float* __restrict__ meanF, const float* __restrict__ xF,
    const float* __restrict__ wlF, const float* __restrict__ wrF,
    const float* __restrict__ bl,
    __half* __restrict__ out_h,      // fp16 row-major output (may be null)
    float* __restrict__ outF) {      // A-frag tf32 output slab array
    extern __shared__ float smem[];
    uint32_t sbase = smem_u32(smem);
    const int t = threadIdx.x;
    const int wid = t >> 5, lid = t & 31;
    const int wm = wid >> 2, wn = wid & 3;
    const int bm = blockIdx.x;
    const int node0 = bm * 128;

    const float* Aslab0 = meanF + (size_t)bm * SLAB;
    const float* Aslab1 = xF + (size_t)bm * SLAB;

    float acc[4][4][4];
#pragma unroll
    for (int i = 0; i < 4; i++)
#pragma unroll
        for (int j = 0; j < 4; j++) {
            acc[i][j][0] = 0.f; acc[i][j][1] = 0.f; acc[i][j][2] = 0.f; acc[i][j][3] = 0.f;
        }

    {
#pragma unroll
        for (int s = 0; s < 4; s++) {
            int o = (t + s * 256) * 4;
            cp16(sbase + o * 4, Aslab0 + o);
            cp16(sbase + 16384 + o * 4, wlF + o);
        }
        CP_COMMIT();
    }

#pragma unroll 1
    for (int ch = 0; ch < 8; ch++) {
        if (ch < 7) {
            int nc = ch + 1;
            const float* A = ((nc < 4) ? Aslab0 : Aslab1) + (nc & 3) * 4096;
            const float* B = ((nc < 4) ? wlF : wrF) + (nc & 3) * 4096;
            uint32_t d = sbase + (uint32_t)((nc & 1) * 32768);
#pragma unroll
            for (int s = 0; s < 4; s++) {
                int o = (t + s * 256) * 4;
                cp16(d + o * 4, A + o);
                cp16(d + 16384 + o * 4, B + o);
            }
            CP_COMMIT();
            CP_WAIT1();
        } else {
            CP_WAIT0();
        }
        __syncthreads();
        const uint32_t* sA = (const uint32_t*)smem + (ch & 1) * 8192;
        const uint32_t* sB = sA + 4096;
        mma_chunk(sA, sB, acc, wm, wn, lid);
        __syncthreads();
    }

    // ---- fused epilogue: stage relu(acc+bias) into smem [128][132] ----
    const int lrow = wm * 64 + (lid >> 2);
    const int cbase = wn * 32 + (lid & 3) * 2;
#pragma unroll
    for (int j = 0; j < 4; j++) {
        int col = cbase + j * 8;
        float b0 = __ldg(&bl[col]), b1 = __ldg(&bl[col + 1]);
#pragma unroll
        for (int i = 0; i < 4; i++) {
            int r0 = lrow + i * 16;
            smem[r0 * 132 + col]     = fmaxf(acc[i][j][0] + b0, 0.f);
            smem[r0 * 132 + col + 1] = fmaxf(acc[i][j][1] + b1, 0.f);
            smem[(r0 + 8) * 132 + col]     = fmaxf(acc[i][j][2] + b0, 0.f);
            smem[(r0 + 8) * 132 + col + 1] = fmaxf(acc[i][j][3] + b1, 0.f);
        }
    }
    __syncthreads();

    if (out_h) {
#pragma unroll
        for (int i = 0; i < 16; i++) {
            int idx = t + i * 256;
            int row = idx >> 5, c4 = (idx & 31) * 4;
            int node = node0 + row;
            if (node < N_NODES) {
                const float* p = &smem[row * 132 + c4];
                *(uint2*)(out_h + (size_t)node * C_DIM + c4) =
                    pack_half4(p[0], p[1], p[2], p[3]);
            }
        }
    }

    float* slab = outF + (size_t)bm * SLAB;
#pragma unroll
    for (int i = 0; i < 16; i++) {
        int w = (t + i * 256) * 4;
        int lane = w & 31, reg = (w >> 5) & 3, tile = (w >> 7) & 7, k8c = w >> 10;
        int row = tile * 16 + (reg & 1) * 8 + (lane >> 2);
        int kb = k8c * 8 + ((reg >> 1) & 1) * 4;
        float4 v = *(const float4*)&smem[row * 132 + kb];
        *(uint4*)(slab + w) = make_uint4(f2tf(v.x), f2tf(v.y), f2tf(v.z), f2tf(v.w));
    }
}

// ---------------- pipelined head: logits (cols 0-63) + value (col 64) ----------------
__global__ __launch_bounds__(256, 2) void head_pipe_kernel(
    const float* __restrict__ hF, const float* __restrict__ headBF,
    const float* __restrict__ ba, const float* __restrict__ bc,
    float* __restrict__ out) {
    extern __shared__ float smem[];
    uint32_t sbase = smem_u32(smem);
    const int t = threadIdx.x;
    const int wid = t >> 5, lid = t & 31;
    const int wm = wid >> 2, wn = wid & 3;
    const int bm = blockIdx.x;
    const int node0 = bm * 128;
    const float* Aslab = hF + (size_t)bm * SLAB;

    float acc[4][4][4];
#pragma unroll
    for (int i = 0; i < 4; i++)
#pragma unroll
        for (int j = 0; j < 4; j++) {
            acc[i][j][0] = 0.f; acc[i][j][1] = 0.f; acc[i][j][2] = 0.f; acc[i][j][3] = 0.f;
        }

    {
#pragma unroll
        for (int s = 0; s < 4; s++) {
            int o = (t + s * 256) * 4;
            cp16(sbase + o * 4, Aslab + o);
            cp16(sbase + 16384 + o * 4, headBF + o);
        }
        CP_COMMIT();
    }
#pragma unroll 1
    for (int ch = 0; ch < 4; ch++) {
        if (ch < 3) {
            int nc = ch + 1;
            uint32_t d = sbase + (uint32_t)((nc & 1) * 32768);
#pragma unroll
            for (int s = 0; s < 4; s++) {
                int o = (t + s * 256) * 4;
                cp16(d + o * 4, Aslab + nc * 4096 + o);
                cp16(d + 16384 + o * 4, headBF + nc * 4096 + o);
            }
            CP_COMMIT();
            CP_WAIT1();
        } else {
            CP_WAIT0();
        }
        __syncthreads();
        const uint32_t* sA = (const uint32_t*)smem + (ch & 1) * 8192;
        const uint32_t* sB = sA + 4096;
        mma_chunk(sA, sB, acc, wm, wn, lid);
        __syncthreads();
    }

    const int rbase = node0 + wm * 64 + (lid >> 2);
    const int cbase = wn * 32 + (lid & 3) * 2;
#pragma unroll
    for (int j = 0; j < 4; j++) {
        int col = cbase + j * 8;
        if (col < 64) {
            float b0 = __ldg(&ba[col]), b1 = __ldg(&ba[col + 1]);
#pragma unroll
            for (int i = 0; i < 4; i++) {
                int n0 = rbase + i * 16;
                if (n0 < N_NODES)
                    *(float2*)(out + (size_t)n0 * OUT_CH + col) =
                        make_float2(acc[i][j][0] + b0, acc[i][j][1] + b1);
                int n1 = n0 + 8;
                if (n1 < N_NODES)
                    *(float2*)(out + (size_t)n1 * OUT_CH + col) =
                        make_float2(acc[i][j][2] + b0, acc[i][j][3] + b1);
            }
        } else if (col == 64) {
            float b0 = __ldg(&bc[0]);
#pragma unroll
            for (int i = 0; i < 4; i++) {
                int n0 = rbase + i * 16;
                if (n0 < N_NODES)
                    out[(size_t)N_NODES * OUT_CH + n0] = acc[i][j][0] + b0;
                int n1 = n0 + 8;
                if (n1 < N_NODES)
                    out[(size_t)N_NODES * OUT_CH + n1] = acc[i][j][2] + b0;
            }
        }
    }
}

// ---------------- launch (single stream, no allocations, no stream objects) ------
extern "C" void kernel_launch(void* const* d_in, const int* in_sizes, int n_in,
                              void* d_out, int out_size) {
    const float* x   = (const float*)d_in[0];
    const void*  ei  = d_in[1];
    const float* w1l = (const float*)d_in[2];
    const float* b1l = (const float*)d_in[3];
    const float* w1r = (const float*)d_in[4];
    const float* w2l = (const float*)d_in[5];
    const float* b2l = (const float*)d_in[6];
    const float* w2r = (const float*)d_in[7];
    const float* wa  = (const float*)d_in[8];
    const float* ba  = (const float*)d_in[9];
    const float* wc  = (const float*)d_in[10];
    const float* bc  = (const float*)d_in[11];
    float* out = (float*)d_out;

    float *meanF, *xF, *h1F, *h2F, *w1lF, *w1rF, *w2lF, *w2rF, *headBF;
    __half *xH, *h1H;
    int *cursor, *csr;
    cudaGetSymbolAddress((void**)&xH,     g_xH);
    cudaGetSymbolAddress((void**)&h1H,    g_h1H);
    cudaGetSymbolAddress((void**)&meanF,  g_meanF);
    cudaGetSymbolAddress((void**)&xF,     g_xF);
    cudaGetSymbolAddress((void**)&h1F,    g_h1F);
    cudaGetSymbolAddress((void**)&h2F,    g_h2F);
    cudaGetSymbolAddress((void**)&w1lF,   g_w1lF);
    cudaGetSymbolAddress((void**)&w1rF,   g_w1rF);
    cudaGetSymbolAddress((void**)&w2lF,   g_w2lF);
    cudaGetSymbolAddress((void**)&w2rF,   g_w2rF);
    cudaGetSymbolAddress((void**)&headBF, g_headBF);
    cudaGetSymbolAddress((void**)&cursor, g_cursor);
    cudaGetSymbolAddress((void**)&csr,    g_csr);

    const int SAGE_SMEM = 128 * 132 * 4;  // 67584 >= 64KB pipeline needs
    const int HEAD_SMEM = 65536;
    cudaFuncSetAttribute(sage_pipe_kernel, cudaFuncAttributeMaxDynamicSharedMemorySize, SAGE_SMEM);
    cudaFuncSetAttribute(head_pipe_kernel, cudaFuncAttributeMaxDynamicSharedMemorySize, HEAD_SMEM);

    detect_kernel<<<1, 32>>>((const int*)ei);
    prepw_kernel<<<80, 256>>>(w1l, w1r, w2l, w2r, wa, wc, w1lF, w1rF, w2lF, w2rF, headBF);
    fill_kernel<<<(N_EDGES + 255) / 256, 256>>>(ei, cursor, csr);
    convertA_kernel<<<NBLK * 4, 256>>>(x, xF, xH);

    const int gather_blocks = (N_NODES * 32) / 256;  // 5000

    // ---- layer 1 ----
    gather_kernel<<<gather_blocks, 256>>>(cursor, csr, xH, meanF, 0);
    sage_pipe_kernel<<<NBLK, 256, SAGE_SMEM>>>(meanF, xF, w1lF, w1rF, b1l, h1H, h1F);

    // ---- layer 2 (last cursor reader restores it to zero for next replay) ----
    gather_kernel<<<gather_blocks, 256>>>(cursor, csr, h1H, meanF, 1);
    sage_pipe_kernel<<<NBLK, 256, SAGE_SMEM>>>(meanF, h1F, w2lF, w2rF, b2l, nullptr, h2F);

    // ---- heads ----
    head_pipe_kernel<<<NBLK, 256, HEAD_SMEM>>>(h2F, headBF, ba, bc, out);
}

// round 11
// speedup vs baseline: 1.0304x; 1.0304x over previous
#include <cuda_runtime.h>
#include <cuda_fp16.h>
#include <cstdint>

#define N_NODES 40000
#define N_EDGES 640000
#define C_DIM   128
#define OUT_CH  64
#define BUCKET  64
#define NBLK    313          // ceil(40000/128)
#define SLAB    16384        // words per 128-row A-frag slab (128x128)

// prep_all block partition
#define PB_CONV 1252                     // NBLK*4 convertA blocks
#define PB_W    (PB_CONV + 80)           // 80 prepw blocks
#define PB_FILL (PB_W + 2500)            // 2500 fill blocks (640000/256)

// ---------------- device scratch (no allocations allowed) ----------------
__device__ __half g_xH[N_NODES * C_DIM];    // fp16 copy of x for gather
__device__ __half g_h1H[N_NODES * C_DIM];   // fp16 copy of h1 for gather
__device__ float g_meanF[NBLK * SLAB];
__device__ float g_xF[NBLK * SLAB];
__device__ float g_h1F[NBLK * SLAB];
__device__ float g_h2F[NBLK * SLAB];
__device__ float g_w1lF[SLAB], g_w1rF[SLAB], g_w2lF[SLAB], g_w2rF[SLAB], g_headBF[SLAB];
__device__ int   g_cursor[N_NODES];   // zero-initialized; self-restored each run
__device__ int   g_csr[N_NODES * BUCKET];

// ---------------- helpers ----------------
__device__ __forceinline__ uint32_t f2tf(float v) {
    uint32_t r; asm("cvt.rna.tf32.f32 %0, %1;" : "=r"(r) : "f"(v)); return r;
}
__device__ __forceinline__ uint32_t smem_u32(const void* p) {
    uint32_t a;
    asm("{ .reg .u64 t; cvta.to.shared.u64 t, %1; cvt.u32.u64 %0, t; }" : "=r"(a) : "l"(p));
    return a;
}
__device__ __forceinline__ void cp16(uint32_t dst, const void* src) {
    asm volatile("cp.async.ca.shared.global [%0], [%1], 16;" :: "r"(dst), "l"(src));
}
#define CP_COMMIT() asm volatile("cp.async.commit_group;" ::: "memory")
#define CP_WAIT1()  asm volatile("cp.async.wait_group 1;" ::: "memory")
#define CP_WAIT0()  asm volatile("cp.async.wait_group 0;" ::: "memory")

__device__ __forceinline__ uint2 pack_half4(float a, float b, float c, float d) {
    __half2 h01 = __floats2half2_rn(a, b);
    __half2 h23 = __floats2half2_rn(c, d);
    uint2 p;
    p.x = *(uint32_t*)&h01;
    p.y = *(uint32_t*)&h23;
    return p;
}

__device__ __forceinline__ void mma_tf32(float& d0, float& d1, float& d2, float& d3,
                                         uint32_t a0, uint32_t a1, uint32_t a2, uint32_t a3,
                                         uint32_t b0, uint32_t b1) {
    asm volatile(
        "mma.sync.aligned.m16n8k8.row.col.f32.tf32.tf32.f32 "
        "{%0,%1,%2,%3}, {%4,%5,%6,%7}, {%8,%9}, {%0,%1,%2,%3};"
        : "+f"(d0), "+f"(d1), "+f"(d2), "+f"(d3)
        : "r"(a0), "r"(a1), "r"(a2), "r"(a3), "r"(b0), "r"(b1));
}

// mma over one staged 128x128x32 chunk; warp tile 64 nodes x 32 outs
// A chunk layout: [k8=4][m_tile=8][reg=4][lane=32]; B: [k8=4][n_tile=16][reg=2][lane=32]
__device__ __forceinline__ void mma_chunk(const uint32_t* sA, const uint32_t* sB,
                                          float acc[4][4][4], int wm, int wn, int lid) {
#pragma unroll
    for (int k8 = 0; k8 < 4; k8++) {
        uint32_t a[4][4], b[4][2];
#pragma unroll
        for (int i = 0; i < 4; i++) {
            uint32_t base = ((k8 * 8 + (wm * 4 + i)) * 4) * 32 + lid;
            a[i][0] = sA[base];      a[i][1] = sA[base + 32];
            a[i][2] = sA[base + 64]; a[i][3] = sA[base + 96];
        }
#pragma unroll
        for (int j = 0; j < 4; j++) {
            uint32_t base = ((k8 * 16 + (wn * 4 + j)) * 2) * 32 + lid;
            b[j][0] = sB[base]; b[j][1] = sB[base + 32];
        }
#pragma unroll
        for (int i = 0; i < 4; i++)
#pragma unroll
            for (int j = 0; j < 4; j++)
                mma_tf32(acc[i][j][0], acc[i][j][1], acc[i][j][2], acc[i][j][3],
                         a[i][0], a[i][1], a[i][2], a[i][3], b[j][0], b[j][1]);
    }
}

// ================= fused prep: convertA + prepw + fill in ONE kernel =================
__global__ __launch_bounds__(256) void prep_all_kernel(
    const float* __restrict__ x, const void* __restrict__ ei,
    const float* __restrict__ w1l, const float* __restrict__ w1r,
    const float* __restrict__ w2l, const float* __restrict__ w2r,
    const float* __restrict__ wa, const float* __restrict__ wc,
    float* __restrict__ xF, __half* __restrict__ xH,
    float* __restrict__ w1lF, float* __restrict__ w1rF,
    float* __restrict__ w2lF, float* __restrict__ w2rF,
    float* __restrict__ headBF,
    int* __restrict__ cursor, int* __restrict__ csr) {
    const int b = blockIdx.x;
    const int t = threadIdx.x;

    if (b < PB_CONV) {
        // ---- convertA: x row-major fp32 -> A-frag tf32 slab + fp16 copy ----
        __shared__ __align__(16) float s[128][36];
        const int bm = b >> 2;
        const int ch = b & 3;
        const int node0 = bm * 128;
        float* slab = xF + (size_t)bm * SLAB;
#pragma unroll
        for (int i = 0; i < 4; i++) {
            int idx = t + i * 256;
            int row = idx >> 3, k4 = (idx & 7) * 4;
            int node = node0 + row;
            bool valid = (node < N_NODES);
            if (!valid) node = N_NODES - 1;
            float4 v = __ldg((const float4*)(x + (size_t)node * C_DIM + ch * 32 + k4));
            *(float4*)&s[row][k4] = v;
            if (valid)
                *(uint2*)(xH + (size_t)node * C_DIM + ch * 32 + k4) =
                    pack_half4(v.x, v.y, v.z, v.w);
        }
        __syncthreads();
#pragma unroll
        for (int i = 0; i < 4; i++) {
            int w = (t + i * 256) * 4;
            int lane = w & 31, reg = (w >> 5) & 3, tile = (w >> 7) & 7, k8 = w >> 10;
            int row = tile * 16 + (reg & 1) * 8 + (lane >> 2);
            int kb = k8 * 8 + ((reg >> 1) & 1) * 4;
            float4 v = *(const float4*)&s[row][kb];
            *(uint4*)(slab + ch * 4096 + w) =
                make_uint4(f2tf(v.x), f2tf(v.y), f2tf(v.z), f2tf(v.w));
        }
    } else if (b < PB_W) {
        // ---- prepw: weights row-major fp32 -> B-frag tf32 ----
        int gid = (b - PB_CONV) * 256 + t;   // 0..20479
        int m = gid >> 12, g = gid & 4095;
        int w = g * 4;
        int lane = w & 31, reg = (w >> 5) & 1, ntile = (w >> 6) & 15, k8 = w >> 10;
        int n = ntile * 8 + (lane >> 2);
        int k = k8 * 8 + reg * 4;
        float4 v = make_float4(0.f, 0.f, 0.f, 0.f);
        float* dst;
        switch (m) {
            case 0: v = __ldg((const float4*)(w1l + (size_t)n * C_DIM + k)); dst = w1lF; break;
            case 1: v = __ldg((const float4*)(w1r + (size_t)n * C_DIM + k)); dst = w1rF; break;
            case 2: v = __ldg((const float4*)(w2l + (size_t)n * C_DIM + k)); dst = w2lF; break;
            case 3: v = __ldg((const float4*)(w2r + (size_t)n * C_DIM + k)); dst = w2rF; break;
            default:
                if (n < 64)       v = __ldg((const float4*)(wa + (size_t)n * C_DIM + k));
                else if (n == 64) v = __ldg((const float4*)(wc + k));
                dst = headBF; break;
        }
        *(uint4*)(dst + w) = make_uint4(f2tf(v.x), f2tf(v.y), f2tf(v.z), f2tf(v.w));
    } else {
        // ---- fill: bucketed CSR build, inline int64/int32 detection ----
        __shared__ int s_is64;
        {
            bool ok = true;
            if (t < 16) {
                int lo = ((const int*)ei)[2 * t];
                int hi = ((const int*)ei)[2 * t + 1];
                ok = (hi == 0) && ((unsigned)lo < (unsigned)N_NODES);
            }
            unsigned m = __ballot_sync(0xffffffffu, ok);
            if (t == 0) s_is64 = (m == 0xffffffffu) ? 1 : 0;
        }
        __syncthreads();
        int is64 = s_is64;
        int e = (b - PB_W) * 256 + t;        // 0..639999 exactly
        int src, dst;
        if (is64) {
            src = (int)((const long long*)ei)[e];
            dst = (int)((const long long*)ei)[N_EDGES + e];
        } else {
            src = ((const int*)ei)[e];
            dst = ((const int*)ei)[N_EDGES + e];
        }
        int pos = atomicAdd(&cursor[dst], 1);
        if (pos < BUCKET) csr[dst * BUCKET + pos] = src;
    }
}

// ---------------- mean aggregation: warp per node, fp16 sources, fp32 accum ----
// MLP=4 (four independent row loads in flight). Optionally restores cursor=0.
__global__ __launch_bounds__(256) void gather_kernel(int* __restrict__ cursor,
                                                     const int* __restrict__ csr,
                                                     const __half* __restrict__ xh,
                                                     float* __restrict__ meanF,
                                                     int zero_cursor) {
    int gt = blockIdx.x * blockDim.x + threadIdx.x;
    int n = gt >> 5;
    if (n >= N_NODES) return;
    int lane = gt & 31;
    int deg = __ldg(&cursor[n]);
    if (zero_cursor && lane == 0) cursor[n] = 0;   // restore for next replay's fill
    int e = (deg < BUCKET) ? deg : BUCKET;
    const int* bkt = csr + n * BUCKET;
    float4 acc = make_float4(0.f, 0.f, 0.f, 0.f);
    int i = 0;
    for (; i + 4 <= e; i += 4) {
        int s0 = __ldg(&bkt[i + 0]);
        int s1 = __ldg(&bkt[i + 1]);
        int s2 = __ldg(&bkt[i + 2]);
        int s3 = __ldg(&bkt[i + 3]);
        uint2 u0 = __ldg((const uint2*)(xh + (size_t)s0 * C_DIM) + lane);
        uint2 u1 = __ldg((const uint2*)(xh + (size_t)s1 * C_DIM) + lane);
        uint2 u2 = __ldg((const uint2*)(xh + (size_t)s2 * C_DIM) + lane);
        uint2 u3 = __ldg((const uint2*)(xh + (size_t)s3 * C_DIM) + lane);
        float2 a0 = __half22float2(*(__half2*)&u0.x), b0 = __half22float2(*(__half2*)&u0.y);
        float2 a1 = __half22float2(*(__half2*)&u1.x), b1 = __half22float2(*(__half2*)&u1.y);
        float2 a2 = __half22float2(*(__half2*)&u2.x), b2 = __half22float2(*(__half2*)&u2.y);
        float2 a3 = __half22float2(*(__half2*)&u3.x), b3 = __half22float2(*(__half2*)&u3.y);
        acc.x += a0.x + a1.x + a2.x + a3.x;
        acc.y += a0.y + a1.y + a2.y + a3.y;
        acc.z += b0.x + b1.x + b2.x + b3.x;
        acc.w += b0.y + b1.y + b2.y + b3.y;
    }
    for (; i < e; i++) {
        int s0 = __ldg(&bkt[i]);
        uint2 u0 = __ldg((const uint2*)(xh + (size_t)s0 * C_DIM) + lane);
        float2 a0 = __half22float2(*(__half2*)&u0.x), b0 = __half22float2(*(__half2*)&u0.y);
        acc.x += a0.x; acc.y += a0.y; acc.z += b0.x; acc.w += b0.y;
    }
    float inv = 1.0f / fmaxf((float)deg, 1.0f);
    // frag write: lane holds k = 4*lane..4*lane+3 for row r = n&127
    int bm = n >> 7, r = n & 127;
    int k8 = lane >> 1;
    int reg = ((r >> 3) & 1) | ((lane & 1) << 1);
    int tile = (r >> 4) & 7;
    size_t base = (size_t)bm * SLAB + (((k8 * 8 + tile) * 4 + reg) * 32) + ((r & 7) * 4);
    *(uint4*)(meanF + base) = make_uint4(f2tf(acc.x * inv), f2tf(acc.y * inv),
                                         f2tf(acc.z * inv), f2tf(acc.w * inv));
}

// ---------------- pipelined tf32 SAGE GEMM + fused epilogue conversion ----------
__global__ __launch_bounds__(256, 2) void sage_pipe_kernel(
    const float* __restrict__ meanF, const float* __restrict__ xF,
    const float* __restrict__ wlF, const float* __restrict__ wrF,
    const float* __restrict__ bl,
    __half* __restrict__ out_h,      // fp16 row-major output (may be null)
    float* __restrict__ outF) {      // A-frag tf32 output slab array
    extern __shared__ float smem[];
    uint32_t sbase = smem_u32(smem);
    const int t = threadIdx.x;
    const int wid = t >> 5, lid = t & 31;
    const int wm = wid >> 2, wn = wid & 3;
    const int bm = blockIdx.x;
    const int node0 = bm * 128;

    const float* Aslab0 = meanF + (size_t)bm * SLAB;
    const float* Aslab1 = xF + (size_t)bm * SLAB;

    float acc[4][4][4];
#pragma unroll
    for (int i = 0; i < 4; i++)
#pragma unroll
        for (int j = 0; j < 4; j++) {
            acc[i][j][0] = 0.f; acc[i][j][1] = 0.f; acc[i][j][2] = 0.f; acc[i][j][3] = 0.f;
        }

    {
#pragma unroll
        for (int s = 0; s < 4; s++) {
            int o = (t + s * 256) * 4;
            cp16(sbase + o * 4, Aslab0 + o);
            cp16(sbase + 16384 + o * 4, wlF + o);
        }
        CP_COMMIT();
    }

#pragma unroll 1
    for (int ch = 0; ch < 8; ch++) {
        if (ch < 7) {
            int nc = ch + 1;
            const float* A = ((nc < 4) ? Aslab0 : Aslab1) + (nc & 3) * 4096;
            const float* B = ((nc < 4) ? wlF : wrF) + (nc & 3) * 4096;
            uint32_t d = sbase + (uint32_t)((nc & 1) * 32768);
#pragma unroll
            for (int s = 0; s < 4; s++) {
                int o = (t + s * 256) * 4;
                cp16(d + o * 4, A + o);
                cp16(d + 16384 + o * 4, B + o);
            }
            CP_COMMIT();
            CP_WAIT1();
        } else {
            CP_WAIT0();
        }
        __syncthreads();
        const uint32_t* sA = (const uint32_t*)smem + (ch & 1) * 8192;
        const uint32_t* sB = sA + 4096;
        mma_chunk(sA, sB, acc, wm, wn, lid);
        __syncthreads();
    }

    // ---- fused epilogue: stage relu(acc+bias) into smem [128][132] ----
    const int lrow = wm * 64 + (lid >> 2);
    const int cbase = wn * 32 + (lid & 3) * 2;
#pragma unroll
    for (int j = 0; j < 4; j++) {
        int col = cbase + j * 8;
        float b0 = __ldg(&bl[col]), b1 = __ldg(&bl[col + 1]);
#pragma unroll
        for (int i = 0; i < 4; i++) {
            int r0 = lrow + i * 16;
            smem[r0 * 132 + col]     = fmaxf(acc[i][j][0] + b0, 0.f);
            smem[r0 * 132 + col + 1] = fmaxf(acc[i][j][1] + b1, 0.f);
            smem[(r0 + 8) * 132 + col]     = fmaxf(acc[i][j][2] + b0, 0.f);
            smem[(r0 + 8) * 132 + col + 1] = fmaxf(acc[i][j][3] + b1, 0.f);
        }
    }
    __syncthreads();

    if (out_h) {
#pragma unroll
        for (int i = 0; i < 16; i++) {
            int idx = t + i * 256;
            int row = idx >> 5, c4 = (idx & 31) * 4;
            int node = node0 + row;
            if (node < N_NODES) {
                const float* p = &smem[row * 132 + c4];
                *(uint2*)(out_h + (size_t)node * C_DIM + c4) =
                    pack_half4(p[0], p[1], p[2], p[3]);
            }
        }
    }

    float* slab = outF + (size_t)bm * SLAB;
#pragma unroll
    for (int i = 0; i < 16; i++) {
        int w = (t + i * 256) * 4;
        int lane = w & 31, reg = (w >> 5) & 3, tile = (w >> 7) & 7, k8c = w >> 10;
        int row = tile * 16 + (reg & 1) * 8 + (lane >> 2);
        int kb = k8c * 8 + ((reg >> 1) & 1) * 4;
        float4 v = *(const float4*)&smem[row * 132 + kb];
        *(uint4*)(slab + w) = make_uint4(f2tf(v.x), f2tf(v.y), f2tf(v.z), f2tf(v.w));
    }
}

// ---------------- pipelined head: logits (cols 0-63) + value (col 64) ----------------
__global__ __launch_bounds__(256, 2) void head_pipe_kernel(
    const float* __restrict__ hF, const float* __restrict__ headBF,
    const float* __restrict__ ba, const float* __restrict__ bc,
    float* __restrict__ out) {
    extern __shared__ float smem[];
    uint32_t sbase = smem_u32(smem);
    const int t = threadIdx.x;
    const int wid = t >> 5, lid = t & 31;
    const int wm = wid >> 2, wn = wid & 3;
    const int bm = blockIdx.x;
    const int node0 = bm * 128;
    const float* Aslab = hF + (size_t)bm * SLAB;

    float acc[4][4][4];
#pragma unroll
    for (int i = 0; i < 4; i++)
#pragma unroll
        for (int j = 0; j < 4; j++) {
            acc[i][j][0] = 0.f; acc[i][j][1] = 0.f; acc[i][j][2] = 0.f; acc[i][j][3] = 0.f;
        }

    {
#pragma unroll
        for (int s = 0; s < 4; s++) {
            int o = (t + s * 256) * 4;
            cp16(sbase + o * 4, Aslab + o);
            cp16(sbase + 16384 + o * 4, headBF + o);
        }
        CP_COMMIT();
    }
#pragma unroll 1
    for (int ch = 0; ch < 4; ch++) {
        if (ch < 3) {
            int nc = ch + 1;
            uint32_t d = sbase + (uint32_t)((nc & 1) * 32768);
#pragma unroll
            for (int s = 0; s < 4; s++) {
                int o = (t + s * 256) * 4;
                cp16(d + o * 4, Aslab + nc * 4096 + o);
                cp16(d + 16384 + o * 4, headBF + nc * 4096 + o);
            }
            CP_COMMIT();
            CP_WAIT1();
        } else {
            CP_WAIT0();
        }
        __syncthreads();
        const uint32_t* sA = (const uint32_t*)smem + (ch & 1) * 8192;
        const uint32_t* sB = sA + 4096;
        mma_chunk(sA, sB, acc, wm, wn, lid);
        __syncthreads();
    }

    const int rbase = node0 + wm * 64 + (lid >> 2);
    const int cbase = wn * 32 + (lid & 3) * 2;
#pragma unroll
    for (int j = 0; j < 4; j++) {
        int col = cbase + j * 8;
        if (col < 64) {
            float b0 = __ldg(&ba[col]), b1 = __ldg(&ba[col + 1]);
#pragma unroll
            for (int i = 0; i < 4; i++) {
                int n0 = rbase + i * 16;
                if (n0 < N_NODES)
                    *(float2*)(out + (size_t)n0 * OUT_CH + col) =
                        make_float2(acc[i][j][0] + b0, acc[i][j][1] + b1);
                int n1 = n0 + 8;
                if (n1 < N_NODES)
                    *(float2*)(out + (size_t)n1 * OUT_CH + col) =
                        make_float2(acc[i][j][2] + b0, acc[i][j][3] + b1);
            }
        } else if (col == 64) {
            float b0 = __ldg(&bc[0]);
#pragma unroll
            for (int i = 0; i < 4; i++) {
                int n0 = rbase + i * 16;
                if (n0 < N_NODES)
                    out[(size_t)N_NODES * OUT_CH + n0] = acc[i][j][0] + b0;
                int n1 = n0 + 8;
                if (n1 < N_NODES)
                    out[(size_t)N_NODES * OUT_CH + n1] = acc[i][j][2] + b0;
            }
        }
    }
}

// ---------------- launch (single stream, 6 launches, no allocations) ------
extern "C" void kernel_launch(void* const* d_in, const int* in_sizes, int n_in,
                              void* d_out, int out_size) {
    const float* x   = (const float*)d_in[0];
    const void*  ei  = d_in[1];
    const float* w1l = (const float*)d_in[2];
    const float* b1l = (const float*)d_in[3];
    const float* w1r = (const float*)d_in[4];
    const float* w2l = (const float*)d_in[5];
    const float* b2l = (const float*)d_in[6];
    const float* w2r = (const float*)d_in[7];
    const float* wa  = (const float*)d_in[8];
    const float* ba  = (const float*)d_in[9];
    const float* wc  = (const float*)d_in[10];
    const float* bc  = (const float*)d_in[11];
    float* out = (float*)d_out;

    float *meanF, *xF, *h1F, *h2F, *w1lF, *w1rF, *w2lF, *w2rF, *headBF;
    __half *xH, *h1H;
    int *cursor, *csr;
    cudaGetSymbolAddress((void**)&xH,     g_xH);
    cudaGetSymbolAddress((void**)&h1H,    g_h1H);
    cudaGetSymbolAddress((void**)&meanF,  g_meanF);
    cudaGetSymbolAddress((void**)&xF,     g_xF);
    cudaGetSymbolAddress((void**)&h1F,    g_h1F);
    cudaGetSymbolAddress((void**)&h2F,    g_h2F);
    cudaGetSymbolAddress((void**)&w1lF,   g_w1lF);
    cudaGetSymbolAddress((void**)&w1rF,   g_w1rF);
    cudaGetSymbolAddress((void**)&w2lF,   g_w2lF);
    cudaGetSymbolAddress((void**)&w2rF,   g_w2rF);
    cudaGetSymbolAddress((void**)&headBF, g_headBF);
    cudaGetSymbolAddress((void**)&cursor, g_cursor);
    cudaGetSymbolAddress((void**)&csr,    g_csr);

    const int SAGE_SMEM = 128 * 132 * 4;  // 67584 >= 64KB pipeline needs
    const int HEAD_SMEM = 65536;
    cudaFuncSetAttribute(sage_pipe_kernel, cudaFuncAttributeMaxDynamicSharedMemorySize, SAGE_SMEM);
    cudaFuncSetAttribute(head_pipe_kernel, cudaFuncAttributeMaxDynamicSharedMemorySize, HEAD_SMEM);

    // ---- all prep in one wide kernel (convertA | prepw | fill) ----
    prep_all_kernel<<<PB_FILL, 256>>>(x, ei, w1l, w1r, w2l, w2r, wa, wc,
                                      xF, xH, w1lF, w1rF, w2lF, w2rF, headBF,
                                      cursor, csr);

    const int gather_blocks = (N_NODES * 32) / 256;  // 5000

    // ---- layer 1 ----
    gather_kernel<<<gather_blocks, 256>>>(cursor, csr, xH, meanF, 0);
    sage_pipe_kernel<<<NBLK, 256, SAGE_SMEM>>>(meanF, xF, w1lF, w1rF, b1l, h1H, h1F);

    // ---- layer 2 (last cursor reader restores it to zero for next replay) ----
    gather_kernel<<<gather_blocks, 256>>>(cursor, csr, h1H, meanF, 1);
    sage_pipe_kernel<<<NBLK, 256, SAGE_SMEM>>>(meanF, h1F, w2lF, w2rF, b2l, nullptr, h2F);

    // ---- heads ----
    head_pipe_kernel<<<NBLK, 256, HEAD_SMEM>>>(h2F, headBF, ba, bc, out);
}

// round 12
// speedup vs baseline: 1.0663x; 1.0349x over previous
#include <cuda_runtime.h>
#include <cuda_fp16.h>
#include <cstdint>

#define N_NODES 40000
#define N_EDGES 640000
#define C_DIM   128
#define OUT_CH  64
#define BUCKET  64
#define NBLK    313          // ceil(40000/128)
#define SLAB    16384        // words per 128-row A-frag slab (128x128)

// prep_all block partition
#define PB_CONV 1252                     // NBLK*4 convertA blocks
#define PB_W    (PB_CONV + 80)           // 80 prepw blocks
#define PB_FILL (PB_W + 2500)            // 2500 fill blocks (640000/256)

// ---------------- device scratch (no allocations allowed) ----------------
__device__ __half g_xH[N_NODES * C_DIM];    // fp16 copy of x for gather
__device__ __half g_h1H[N_NODES * C_DIM];   // fp16 copy of h1 for gather
__device__ float g_meanF[NBLK * SLAB];
__device__ float g_xF[NBLK * SLAB];
__device__ float g_h1F[NBLK * SLAB];
__device__ float g_h2F[NBLK * SLAB];
__device__ float g_w1lF[SLAB], g_w1rF[SLAB], g_w2lF[SLAB], g_w2rF[SLAB], g_headBF[SLAB];
__device__ int   g_cursor[N_NODES];   // zero-initialized; self-restored each run
__device__ int   g_csr[N_NODES * BUCKET];

// ---------------- helpers ----------------
__device__ __forceinline__ uint32_t f2tf(float v) {
    uint32_t r; asm("cvt.rna.tf32.f32 %0, %1;" : "=r"(r) : "f"(v)); return r;
}
__device__ __forceinline__ uint32_t smem_u32(const void* p) {
    uint32_t a;
    asm("{ .reg .u64 t; cvta.to.shared.u64 t, %1; cvt.u32.u64 %0, t; }" : "=r"(a) : "l"(p));
    return a;
}
__device__ __forceinline__ void cp16(uint32_t dst, const void* src) {
    asm volatile("cp.async.ca.shared.global [%0], [%1], 16;" :: "r"(dst), "l"(src));
}
#define CP_COMMIT() asm volatile("cp.async.commit_group;" ::: "memory")
#define CP_WAIT1()  asm volatile("cp.async.wait_group 1;" ::: "memory")
#define CP_WAIT0()  asm volatile("cp.async.wait_group 0;" ::: "memory")

__device__ __forceinline__ uint2 pack_half4(float a, float b, float c, float d) {
    __half2 h01 = __floats2half2_rn(a, b);
    __half2 h23 = __floats2half2_rn(c, d);
    uint2 p;
    p.x = *(uint32_t*)&h01;
    p.y = *(uint32_t*)&h23;
    return p;
}

__device__ __forceinline__ void mma_tf32(float& d0, float& d1, float& d2, float& d3,
                                         uint32_t a0, uint32_t a1, uint32_t a2, uint32_t a3,
                                         uint32_t b0, uint32_t b1) {
    asm volatile(
        "mma.sync.aligned.m16n8k8.row.col.f32.tf32.tf32.f32 "
        "{%0,%1,%2,%3}, {%4,%5,%6,%7}, {%8,%9}, {%0,%1,%2,%3};"
        : "+f"(d0), "+f"(d1), "+f"(d2), "+f"(d3)
        : "r"(a0), "r"(a1), "r"(a2), "r"(a3), "r"(b0), "r"(b1));
}

// mma over one staged 128x128x32 chunk; warp tile 64 nodes x 32 outs
// A chunk layout: [k8=4][m_tile=8][reg=4][lane=32]; B: [k8=4][n_tile=16][reg=2][lane=32]
__device__ __forceinline__ void mma_chunk(const uint32_t* sA, const uint32_t* sB,
                                          float acc[4][4][4], int wm, int wn, int lid) {
#pragma unroll
    for (int k8 = 0; k8 < 4; k8++) {
        uint32_t a[4][4], b[4][2];
#pragma unroll
        for (int i = 0; i < 4; i++) {
            uint32_t base = ((k8 * 8 + (wm * 4 + i)) * 4) * 32 + lid;
            a[i][0] = sA[base];      a[i][1] = sA[base + 32];
            a[i][2] = sA[base + 64]; a[i][3] = sA[base + 96];
        }
#pragma unroll
        for (int j = 0; j < 4; j++) {
            uint32_t base = ((k8 * 16 + (wn * 4 + j)) * 2) * 32 + lid;
            b[j][0] = sB[base]; b[j][1] = sB[base + 32];
        }
#pragma unroll
        for (int i = 0; i < 4; i++)
#pragma unroll
            for (int j = 0; j < 4; j++)
                mma_tf32(acc[i][j][0], acc[i][j][1], acc[i][j][2], acc[i][j][3],
                         a[i][0], a[i][1], a[i][2], a[i][3], b[j][0], b[j][1]);
    }
}

// ================= fused prep: convertA + prepw + fill in ONE kernel =================
__global__ __launch_bounds__(256) void prep_all_kernel(
    const float* __restrict__ x, const void* __restrict__ ei,
    const float* __restrict__ w1l, const float* __restrict__ w1r,
    const float* __restrict__ w2l, const float* __restrict__ w2r,
    const float* __restrict__ wa, const float* __restrict__ wc,
    float* __restrict__ xF, __half* __restrict__ xH,
    float* __restrict__ w1lF, float* __restrict__ w1rF,
    float* __restrict__ w2lF, float* __restrict__ w2rF,
    float* __restrict__ headBF,
    int* __restrict__ cursor, int* __restrict__ csr) {
    const int b = blockIdx.x;
    const int t = threadIdx.x;

    if (b < PB_CONV) {
        // ---- convertA: x row-major fp32 -> A-frag tf32 slab + fp16 copy ----
        __shared__ __align__(16) float s[128][36];
        const int bm = b >> 2;
        const int ch = b & 3;
        const int node0 = bm * 128;
        float* slab = xF + (size_t)bm * SLAB;
#pragma unroll
        for (int i = 0; i < 4; i++) {
            int idx = t + i * 256;
            int row = idx >> 3, k4 = (idx & 7) * 4;
            int node = node0 + row;
            bool valid = (node < N_NODES);
            if (!valid) node = N_NODES - 1;
            float4 v = __ldg((const float4*)(x + (size_t)node * C_DIM + ch * 32 + k4));
            *(float4*)&s[row][k4] = v;
            if (valid)
                *(uint2*)(xH + (size_t)node * C_DIM + ch * 32 + k4) =
                    pack_half4(v.x, v.y, v.z, v.w);
        }
        __syncthreads();
#pragma unroll
        for (int i = 0; i < 4; i++) {
            int w = (t + i * 256) * 4;
            int lane = w & 31, reg = (w >> 5) & 3, tile = (w >> 7) & 7, k8 = w >> 10;
            int row = tile * 16 + (reg & 1) * 8 + (lane >> 2);
            int kb = k8 * 8 + ((reg >> 1) & 1) * 4;
            float4 v = *(const float4*)&s[row][kb];
            *(uint4*)(slab + ch * 4096 + w) =
                make_uint4(f2tf(v.x), f2tf(v.y), f2tf(v.z), f2tf(v.w));
        }
    } else if (b < PB_W) {
        // ---- prepw: weights row-major fp32 -> B-frag tf32 ----
        int gid = (b - PB_CONV) * 256 + t;   // 0..20479
        int m = gid >> 12, g = gid & 4095;
        int w = g * 4;
        int lane = w & 31, reg = (w >> 5) & 1, ntile = (w >> 6) & 15, k8 = w >> 10;
        int n = ntile * 8 + (lane >> 2);
        int k = k8 * 8 + reg * 4;
        float4 v = make_float4(0.f, 0.f, 0.f, 0.f);
        float* dst;
        switch (m) {
            case 0: v = __ldg((const float4*)(w1l + (size_t)n * C_DIM + k)); dst = w1lF; break;
            case 1: v = __ldg((const float4*)(w1r + (size_t)n * C_DIM + k)); dst = w1rF; break;
            case 2: v = __ldg((const float4*)(w2l + (size_t)n * C_DIM + k)); dst = w2lF; break;
            case 3: v = __ldg((const float4*)(w2r + (size_t)n * C_DIM + k)); dst = w2rF; break;
            default:
                if (n < 64)       v = __ldg((const float4*)(wa + (size_t)n * C_DIM + k));
                else if (n == 64) v = __ldg((const float4*)(wc + k));
                dst = headBF; break;
        }
        *(uint4*)(dst + w) = make_uint4(f2tf(v.x), f2tf(v.y), f2tf(v.z), f2tf(v.w));
    } else {
        // ---- fill: bucketed CSR build, inline int64/int32 detection ----
        __shared__ int s_is64;
        {
            bool ok = true;
            if (t < 16) {
                int lo = ((const int*)ei)[2 * t];
                int hi = ((const int*)ei)[2 * t + 1];
                ok = (hi == 0) && ((unsigned)lo < (unsigned)N_NODES);
            }
            unsigned m = __ballot_sync(0xffffffffu, ok);
            if (t == 0) s_is64 = (m == 0xffffffffu) ? 1 : 0;
        }
        __syncthreads();
        int is64 = s_is64;
        int e = (b - PB_W) * 256 + t;        // 0..639999 exactly
        int src, dst;
        if (is64) {
            src = (int)((const long long*)ei)[e];
            dst = (int)((const long long*)ei)[N_EDGES + e];
        } else {
            src = ((const int*)ei)[e];
            dst = ((const int*)ei)[N_EDGES + e];
        }
        int pos = atomicAdd(&cursor[dst], 1);
        if (pos < BUCKET) csr[dst * BUCKET + pos] = src;
    }
}

// ---------------- mean aggregation: warp per node, MLP=8, vector index loads ----
__global__ __launch_bounds__(256) void gather_kernel(int* __restrict__ cursor,
                                                     const int* __restrict__ csr,
                                                     const __half* __restrict__ xh,
                                                     float* __restrict__ meanF,
                                                     int zero_cursor) {
    int gt = blockIdx.x * blockDim.x + threadIdx.x;
    int n = gt >> 5;
    if (n >= N_NODES) return;
    int lane = gt & 31;
    int deg = __ldg(&cursor[n]);
    if (zero_cursor && lane == 0) cursor[n] = 0;   // restore for next replay's fill
    int e = (deg < BUCKET) ? deg : BUCKET;
    const int4* bkt4 = (const int4*)(csr + n * BUCKET);   // 256B-aligned buckets
    float4 acc = make_float4(0.f, 0.f, 0.f, 0.f);
    int i = 0;
    for (; i + 8 <= e; i += 8) {
        int4 ia = __ldg(&bkt4[i >> 2]);
        int4 ib = __ldg(&bkt4[(i >> 2) + 1]);
        // 8 independent row loads in flight (MLP=8)
        uint2 u0 = __ldg((const uint2*)(xh + (size_t)ia.x * C_DIM) + lane);
        uint2 u1 = __ldg((const uint2*)(xh + (size_t)ia.y * C_DIM) + lane);
        uint2 u2 = __ldg((const uint2*)(xh + (size_t)ia.z * C_DIM) + lane);
        uint2 u3 = __ldg((const uint2*)(xh + (size_t)ia.w * C_DIM) + lane);
        uint2 u4 = __ldg((const uint2*)(xh + (size_t)ib.x * C_DIM) + lane);
        uint2 u5 = __ldg((const uint2*)(xh + (size_t)ib.y * C_DIM) + lane);
        uint2 u6 = __ldg((const uint2*)(xh + (size_t)ib.z * C_DIM) + lane);
        uint2 u7 = __ldg((const uint2*)(xh + (size_t)ib.w * C_DIM) + lane);
        float2 p;
        p = __half22float2(*(__half2*)&u0.x); acc.x += p.x; acc.y += p.y;
        p = __half22float2(*(__half2*)&u0.y); acc.z += p.x; acc.w += p.y;
        p = __half22float2(*(__half2*)&u1.x); acc.x += p.x; acc.y += p.y;
        p = __half22float2(*(__half2*)&u1.y); acc.z += p.x; acc.w += p.y;
        p = __half22float2(*(__half2*)&u2.x); acc.x += p.x; acc.y += p.y;
        p = __half22float2(*(__half2*)&u2.y); acc.z += p.x; acc.w += p.y;
        p = __half22float2(*(__half2*)&u3.x); acc.x += p.x; acc.y += p.y;
        p = __half22float2(*(__half2*)&u3.y); acc.z += p.x; acc.w += p.y;
        p = __half22float2(*(__half2*)&u4.x); acc.x += p.x; acc.y += p.y;
        p = __half22float2(*(__half2*)&u4.y); acc.z += p.x; acc.w += p.y;
        p = __half22float2(*(__half2*)&u5.x); acc.x += p.x; acc.y += p.y;
        p = __half22float2(*(__half2*)&u5.y); acc.z += p.x; acc.w += p.y;
        p = __half22float2(*(__half2*)&u6.x); acc.x += p.x; acc.y += p.y;
        p = __half22float2(*(__half2*)&u6.y); acc.z += p.x; acc.w += p.y;
        p = __half22float2(*(__half2*)&u7.x); acc.x += p.x; acc.y += p.y;
        p = __half22float2(*(__half2*)&u7.y); acc.z += p.x; acc.w += p.y;
    }
    if (i + 4 <= e) {
        int4 ia = __ldg(&bkt4[i >> 2]);
        uint2 u0 = __ldg((const uint2*)(xh + (size_t)ia.x * C_DIM) + lane);
        uint2 u1 = __ldg((const uint2*)(xh + (size_t)ia.y * C_DIM) + lane);
        uint2 u2 = __ldg((const uint2*)(xh + (size_t)ia.z * C_DIM) + lane);
        uint2 u3 = __ldg((const uint2*)(xh + (size_t)ia.w * C_DIM) + lane);
        float2 p;
        p = __half22float2(*(__half2*)&u0.x); acc.x += p.x; acc.y += p.y;
        p = __half22float2(*(__half2*)&u0.y); acc.z += p.x; acc.w += p.y;
        p = __half22float2(*(__half2*)&u1.x); acc.x += p.x; acc.y += p.y;
        p = __half22float2(*(__half2*)&u1.y); acc.z += p.x; acc.w += p.y;
        p = __half22float2(*(__half2*)&u2.x); acc.x += p.x; acc.y += p.y;
        p = __half22float2(*(__half2*)&u2.y); acc.z += p.x; acc.w += p.y;
        p = __half22float2(*(__half2*)&u3.x); acc.x += p.x; acc.y += p.y;
        p = __half22float2(*(__half2*)&u3.y); acc.z += p.x; acc.w += p.y;
        i += 4;
    }
    const int* bkt = csr + n * BUCKET;
    for (; i < e; i++) {
        int s0 = __ldg(&bkt[i]);
        uint2 u0 = __ldg((const uint2*)(xh + (size_t)s0 * C_DIM) + lane);
        float2 p;
        p = __half22float2(*(__half2*)&u0.x); acc.x += p.x; acc.y += p.y;
        p = __half22float2(*(__half2*)&u0.y); acc.z += p.x; acc.w += p.y;
    }
    float inv = 1.0f / fmaxf((float)deg, 1.0f);
    // frag write: lane holds k = 4*lane..4*lane+3 for row r = n&127
    int bm = n >> 7, r = n & 127;
    int k8 = lane >> 1;
    int reg = ((r >> 3) & 1) | ((lane & 1) << 1);
    int tile = (r >> 4) & 7;
    size_t base = (size_t)bm * SLAB + (((k8 * 8 + tile) * 4 + reg) * 32) + ((r & 7) * 4);
    *(uint4*)(meanF + base) = make_uint4(f2tf(acc.x * inv), f2tf(acc.y * inv),
                                         f2tf(acc.z * inv), f2tf(acc.w * inv));
}

// ---------------- pipelined tf32 SAGE GEMM + fused epilogue conversion ----------
__global__ __launch_bounds__(256, 2) void sage_pipe_kernel(
    const float* __restrict__ meanF, const float* __restrict__ xF,
    const float* __restrict__ wlF, const float* __restrict__ wrF,
    const float* __restrict__ bl,
    __half* __restrict__ out_h,      // fp16 row-major output (may be null)
    float* __restrict__ outF) {      // A-frag tf32 output slab array
    extern __shared__ float smem[];
    uint32_t sbase = smem_u32(smem);
    const int t = threadIdx.x;
    const int wid = t >> 5, lid = t & 31;
    const int wm = wid >> 2, wn = wid & 3;
    const int bm = blockIdx.x;
    const int node0 = bm * 128;

    const float* Aslab0 = meanF + (size_t)bm * SLAB;
    const float* Aslab1 = xF + (size_t)bm * SLAB;

    float acc[4][4][4];
#pragma unroll
    for (int i = 0; i < 4; i++)
#pragma unroll
        for (int j = 0; j < 4; j++) {
            acc[i][j][0] = 0.f; acc[i][j][1] = 0.f; acc[i][j][2] = 0.f; acc[i][j][3] = 0.f;
        }

    {
#pragma unroll
        for (int s = 0; s < 4; s++) {
            int o = (t + s * 256) * 4;
            cp16(sbase + o * 4, Aslab0 + o);
            cp16(sbase + 16384 + o * 4, wlF + o);
        }
        CP_COMMIT();
    }

#pragma unroll 1
    for (int ch = 0; ch < 8; ch++) {
        if (ch < 7) {
            int nc = ch + 1;
            const float* A = ((nc < 4) ? Aslab0 : Aslab1) + (nc & 3) * 4096;
            const float* B = ((nc < 4) ? wlF : wrF) + (nc & 3) * 4096;
            uint32_t d = sbase + (uint32_t)((nc & 1) * 32768);
#pragma unroll
            for (int s = 0; s < 4; s++) {
                int o = (t + s * 256) * 4;
                cp16(d + o * 4, A + o);
                cp16(d + 16384 + o * 4, B + o);
            }
            CP_COMMIT();
            CP_WAIT1();
        } else {
            CP_WAIT0();
        }
        __syncthreads();
        const uint32_t* sA = (const uint32_t*)smem + (ch & 1) * 8192;
        const uint32_t* sB = sA + 4096;
        mma_chunk(sA, sB, acc, wm, wn, lid);
        __syncthreads();
    }

    // ---- fused epilogue: stage relu(acc+bias) into smem [128][132] ----
    const int lrow = wm * 64 + (lid >> 2);
    const int cbase = wn * 32 + (lid & 3) * 2;
#pragma unroll
    for (int j = 0; j < 4; j++) {
        int col = cbase + j * 8;
        float b0 = __ldg(&bl[col]), b1 = __ldg(&bl[col + 1]);
#pragma unroll
        for (int i = 0; i < 4; i++) {
            int r0 = lrow + i * 16;
            smem[r0 * 132 + col]     = fmaxf(acc[i][j][0] + b0, 0.f);
            smem[r0 * 132 + col + 1] = fmaxf(acc[i][j][1] + b1, 0.f);
            smem[(r0 + 8) * 132 + col]     = fmaxf(acc[i][j][2] + b0, 0.f);
            smem[(r0 + 8) * 132 + col + 1] = fmaxf(acc[i][j][3] + b1, 0.f);
        }
    }
    __syncthreads();

    if (out_h) {
#pragma unroll
        for (int i = 0; i < 16; i++) {
            int idx = t + i * 256;
            int row = idx >> 5, c4 = (idx & 31) * 4;
            int node = node0 + row;
            if (node < N_NODES) {
                const float* p = &smem[row * 132 + c4];
                *(uint2*)(out_h + (size_t)node * C_DIM + c4) =
                    pack_half4(p[0], p[1], p[2], p[3]);
            }
        }
    }

    float* slab = outF + (size_t)bm * SLAB;
#pragma unroll
    for (int i = 0; i < 16; i++) {
        int w = (t + i * 256) * 4;
        int lane = w & 31, reg = (w >> 5) & 3, tile = (w >> 7) & 7, k8c = w >> 10;
        int row = tile * 16 + (reg & 1) * 8 + (lane >> 2);
        int kb = k8c * 8 + ((reg >> 1) & 1) * 4;
        float4 v = *(const float4*)&smem[row * 132 + kb];
        *(uint4*)(slab + w) = make_uint4(f2tf(v.x), f2tf(v.y), f2tf(v.z), f2tf(v.w));
    }
}

// ---------------- pipelined head: logits (cols 0-63) + value (col 64) ----------------
__global__ __launch_bounds__(256, 2) void head_pipe_kernel(
    const float* __restrict__ hF, const float* __restrict__ headBF,
    const float* __restrict__ ba, const float* __restrict__ bc,
    float* __restrict__ out) {
    extern __shared__ float smem[];
    uint32_t sbase = smem_u32(smem);
    const int t = threadIdx.x;
    const int wid = t >> 5, lid = t & 31;
    const int wm = wid >> 2, wn = wid & 3;
    const int bm = blockIdx.x;
    const int node0 = bm * 128;
    const float* Aslab = hF + (size_t)bm * SLAB;

    float acc[4][4][4];
#pragma unroll
    for (int i = 0; i < 4; i++)
#pragma unroll
        for (int j = 0; j < 4; j++) {
            acc[i][j][0] = 0.f; acc[i][j][1] = 0.f; acc[i][j][2] = 0.f; acc[i][j][3] = 0.f;
        }

    {
#pragma unroll
        for (int s = 0; s < 4; s++) {
            int o = (t + s * 256) * 4;
            cp16(sbase + o * 4, Aslab + o);
            cp16(sbase + 16384 + o * 4, headBF + o);
        }
        CP_COMMIT();
    }
#pragma unroll 1
    for (int ch = 0; ch < 4; ch++) {
        if (ch < 3) {
            int nc = ch + 1;
            uint32_t d = sbase + (uint32_t)((nc & 1) * 32768);
#pragma unroll
            for (int s = 0; s < 4; s++) {
                int o = (t + s * 256) * 4;
                cp16(d + o * 4, Aslab + nc * 4096 + o);
                cp16(d + 16384 + o * 4, headBF + nc * 4096 + o);
            }
            CP_COMMIT();
            CP_WAIT1();
        } else {
            CP_WAIT0();
        }
        __syncthreads();
        const uint32_t* sA = (const uint32_t*)smem + (ch & 1) * 8192;
        const uint32_t* sB = sA + 4096;
        mma_chunk(sA, sB, acc, wm, wn, lid);
        __syncthreads();
    }

    const int rbase = node0 + wm * 64 + (lid >> 2);
    const int cbase = wn * 32 + (lid & 3) * 2;
#pragma unroll
    for (int j = 0; j < 4; j++) {
        int col = cbase + j * 8;
        if (col < 64) {
            float b0 = __ldg(&ba[col]), b1 = __ldg(&ba[col + 1]);
#pragma unroll
            for (int i = 0; i < 4; i++) {
                int n0 = rbase + i * 16;
                if (n0 < N_NODES)
                    *(float2*)(out + (size_t)n0 * OUT_CH + col) =
                        make_float2(acc[i][j][0] + b0, acc[i][j][1] + b1);
                int n1 = n0 + 8;
                if (n1 < N_NODES)
                    *(float2*)(out + (size_t)n1 * OUT_CH + col) =
                        make_float2(acc[i][j][2] + b0, acc[i][j][3] + b1);
            }
        } else if (col == 64) {
            float b0 = __ldg(&bc[0]);
#pragma unroll
            for (int i = 0; i < 4; i++) {
                int n0 = rbase + i * 16;
                if (n0 < N_NODES)
                    out[(size_t)N_NODES * OUT_CH + n0] = acc[i][j][0] + b0;
                int n1 = n0 + 8;
                if (n1 < N_NODES)
                    out[(size_t)N_NODES * OUT_CH + n1] = acc[i][j][2] + b0;
            }
        }
    }
}

// ---------------- launch (single stream, 6 launches, no allocations) ------
extern "C" void kernel_launch(void* const* d_in, const int* in_sizes, int n_in,
                              void* d_out, int out_size) {
    const float* x   = (const float*)d_in[0];
    const void*  ei  = d_in[1];
    const float* w1l = (const float*)d_in[2];
    const float* b1l = (const float*)d_in[3];
    const float* w1r = (const float*)d_in[4];
    const float* w2l = (const float*)d_in[5];
    const float* b2l = (const float*)d_in[6];
    const float* w2r = (const float*)d_in[7];
    const float* wa  = (const float*)d_in[8];
    const float* ba  = (const float*)d_in[9];
    const float* wc  = (const float*)d_in[10];
    const float* bc  = (const float*)d_in[11];
    float* out = (float*)d_out;

    float *meanF, *xF, *h1F, *h2F, *w1lF, *w1rF, *w2lF, *w2rF, *headBF;
    __half *xH, *h1H;
    int *cursor, *csr;
    cudaGetSymbolAddress((void**)&xH,     g_xH);
    cudaGetSymbolAddress((void**)&h1H,    g_h1H);
    cudaGetSymbolAddress((void**)&meanF,  g_meanF);
    cudaGetSymbolAddress((void**)&xF,     g_xF);
    cudaGetSymbolAddress((void**)&h1F,    g_h1F);
    cudaGetSymbolAddress((void**)&h2F,    g_h2F);
    cudaGetSymbolAddress((void**)&w1lF,   g_w1lF);
    cudaGetSymbolAddress((void**)&w1rF,   g_w1rF);
    cudaGetSymbolAddress((void**)&w2lF,   g_w2lF);
    cudaGetSymbolAddress((void**)&w2rF,   g_w2rF);
    cudaGetSymbolAddress((void**)&headBF, g_headBF);
    cudaGetSymbolAddress((void**)&cursor, g_cursor);
    cudaGetSymbolAddress((void**)&csr,    g_csr);

    const int SAGE_SMEM = 128 * 132 * 4;  // 67584 >= 64KB pipeline needs
    const int HEAD_SMEM = 65536;
    cudaFuncSetAttribute(sage_pipe_kernel, cudaFuncAttributeMaxDynamicSharedMemorySize, SAGE_SMEM);
    cudaFuncSetAttribute(head_pipe_kernel, cudaFuncAttributeMaxDynamicSharedMemorySize, HEAD_SMEM);

    // ---- all prep in one wide kernel (convertA | prepw | fill) ----
    prep_all_kernel<<<PB_FILL, 256>>>(x, ei, w1l, w1r, w2l, w2r, wa, wc,
                                      xF, xH, w1lF, w1rF, w2lF, w2rF, headBF,
                                      cursor, csr);

    const int gather_blocks = (N_NODES * 32) / 256;  // 5000

    // ---- layer 1 ----
    gather_kernel<<<gather_blocks, 256>>>(cursor, csr, xH, meanF, 0);
    sage_pipe_kernel<<<NBLK, 256, SAGE_SMEM>>>(meanF, xF, w1lF, w1rF, b1l, h1H, h1F);

    // ---- layer 2 (last cursor reader restores it to zero for next replay) ----
    gather_kernel<<<gather_blocks, 256>>>(cursor, csr, h1H, meanF, 1);
    sage_pipe_kernel<<<NBLK, 256, SAGE_SMEM>>>(meanF, h1F, w2lF, w2rF, b2l, nullptr, h2F);

    // ---- heads ----
    head_pipe_kernel<<<NBLK, 256, HEAD_SMEM>>>(h2F, headBF, ba, bc, out);
}

// round 14
// speedup vs baseline: 1.4358x; 1.3465x over previous
#include <cuda_runtime.h>
#include <cuda_fp16.h>
#include <cstdint>

#define N_NODES 40000
#define N_EDGES 640000
#define C_DIM   128
#define OUT_CH  64
#define BUCKET  64
#define NBLK    313          // ceil(40000/128)
#define SLAB    16384        // words per 128-row A-frag slab (128x128)

// prep_all block partition
#define PB_CONV 1252                     // NBLK*4 convertA blocks
#define PB_W    (PB_CONV + 80)           // 80 prepw blocks
#define PB_FILL (PB_W + 2500)            // 2500 fill blocks (640000/256)

// ---------------- device scratch (no allocations allowed) ----------------
__device__ __half g_xH[N_NODES * C_DIM];    // fp16 copy of x for gather
__device__ __half g_h1H[N_NODES * C_DIM];   // fp16 copy of h1 for gather
__device__ float g_meanF[NBLK * SLAB];
__device__ float g_xF[NBLK * SLAB];
__device__ float g_h1F[NBLK * SLAB];
__device__ float g_h2F[NBLK * SLAB];
__device__ float g_w1lF[SLAB], g_w1rF[SLAB], g_w2lF[SLAB], g_w2rF[SLAB], g_headBF[SLAB];
__device__ int   g_cursor[N_NODES];   // zero-initialized; self-restored each run
__device__ int   g_csr[N_NODES * BUCKET];

// ---------------- helpers ----------------
__device__ __forceinline__ uint32_t f2tf(float v) {
    uint32_t r; asm("cvt.rna.tf32.f32 %0, %1;" : "=r"(r) : "f"(v)); return r;
}
__device__ __forceinline__ uint32_t smem_u32(const void* p) {
    uint32_t a;
    asm("{ .reg .u64 t; cvta.to.shared.u64 t, %1; cvt.u32.u64 %0, t; }" : "=r"(a) : "l"(p));
    return a;
}
__device__ __forceinline__ void cp16(uint32_t dst, const void* src) {
    asm volatile("cp.async.ca.shared.global [%0], [%1], 16;" :: "r"(dst), "l"(src));
}
#define CP_COMMIT() asm volatile("cp.async.commit_group;" ::: "memory")
#define CP_WAIT1()  asm volatile("cp.async.wait_group 1;" ::: "memory")
#define CP_WAIT0()  asm volatile("cp.async.wait_group 0;" ::: "memory")

__device__ __forceinline__ uint2 pack_half4(float a, float b, float c, float d) {
    __half2 h01 = __floats2half2_rn(a, b);
    __half2 h23 = __floats2half2_rn(c, d);
    uint2 p;
    p.x = *(uint32_t*)&h01;
    p.y = *(uint32_t*)&h23;
    return p;
}

__device__ __forceinline__ void mma_tf32(float& d0, float& d1, float& d2, float& d3,
                                         uint32_t a0, uint32_t a1, uint32_t a2, uint32_t a3,
                                         uint32_t b0, uint32_t b1) {
    asm volatile(
        "mma.sync.aligned.m16n8k8.row.col.f32.tf32.tf32.f32 "
        "{%0,%1,%2,%3}, {%4,%5,%6,%7}, {%8,%9}, {%0,%1,%2,%3};"
        : "+f"(d0), "+f"(d1), "+f"(d2), "+f"(d3)
        : "r"(a0), "r"(a1), "r"(a2), "r"(a3), "r"(b0), "r"(b1));
}

// mma over one staged 128x128x32 chunk; warp tile 64 nodes x 32 outs
// A chunk layout: [k8=4][m_tile=8][reg=4][lane=32]; B: [k8=4][n_tile=16][reg=2][lane=32]
__device__ __forceinline__ void mma_chunk(const uint32_t* sA, const uint32_t* sB,
                                          float acc[4][4][4], int wm, int wn, int lid) {
#pragma unroll
    for (int k8 = 0; k8 < 4; k8++) {
        uint32_t a[4][4], b[4][2];
#pragma unroll
        for (int i = 0; i < 4; i++) {
            uint32_t base = ((k8 * 8 + (wm * 4 + i)) * 4) * 32 + lid;
            a[i][0] = sA[base];      a[i][1] = sA[base + 32];
            a[i][2] = sA[base + 64]; a[i][3] = sA[base + 96];
        }
#pragma unroll
        for (int j = 0; j < 4; j++) {
            uint32_t base = ((k8 * 16 + (wn * 4 + j)) * 2) * 32 + lid;
            b[j][0] = sB[base]; b[j][1] = sB[base + 32];
        }
#pragma unroll
        for (int i = 0; i < 4; i++)
#pragma unroll
            for (int j = 0; j < 4; j++)
                mma_tf32(acc[i][j][0], acc[i][j][1], acc[i][j][2], acc[i][j][3],
                         a[i][0], a[i][1], a[i][2], a[i][3], b[j][0], b[j][1]);
    }
}

// ================= fused prep: convertA + prepw + fill in ONE kernel =================
__global__ __launch_bounds__(256) void prep_all_kernel(
    const float* __restrict__ x, const void* __restrict__ ei,
    const float* __restrict__ w1l, const float* __restrict__ w1r,
    const float* __restrict__ w2l, const float* __restrict__ w2r,
    const float* __restrict__ wa, const float* __restrict__ wc,
    float* __restrict__ xF, __half* __restrict__ xH,
    float* __restrict__ w1lF, float* __restrict__ w1rF,
    float* __restrict__ w2lF, float* __restrict__ w2rF,
    float* __restrict__ headBF,
    int* __restrict__ cursor, int* __restrict__ csr) {
    const int b = blockIdx.x;
    const int t = threadIdx.x;

    if (b < PB_CONV) {
        // ---- convertA: x row-major fp32 -> A-frag tf32 slab + fp16 copy ----
        __shared__ __align__(16) float s[128][36];
        const int bm = b >> 2;
        const int ch = b & 3;
        const int node0 = bm * 128;
        float* slab = xF + (size_t)bm * SLAB;
#pragma unroll
        for (int i = 0; i < 4; i++) {
            int idx = t + i * 256;
            int row = idx >> 3, k4 = (idx & 7) * 4;
            int node = node0 + row;
            bool valid = (node < N_NODES);
            if (!valid) node = N_NODES - 1;
            float4 v = __ldg((const float4*)(x + (size_t)node * C_DIM + ch * 32 + k4));
            *(float4*)&s[row][k4] = v;
            if (valid)
                *(uint2*)(xH + (size_t)node * C_DIM + ch * 32 + k4) =
                    pack_half4(v.x, v.y, v.z, v.w);
        }
        __syncthreads();
#pragma unroll
        for (int i = 0; i < 4; i++) {
            int w = (t + i * 256) * 4;
            int lane = w & 31, reg = (w >> 5) & 3, tile = (w >> 7) & 7, k8 = w >> 10;
            int row = tile * 16 + (reg & 1) * 8 + (lane >> 2);
            int kb = k8 * 8 + ((reg >> 1) & 1) * 4;
            float4 v = *(const float4*)&s[row][kb];
            *(uint4*)(slab + ch * 4096 + w) =
                make_uint4(f2tf(v.x), f2tf(v.y), f2tf(v.z), f2tf(v.w));
        }
    } else if (b < PB_W) {
        // ---- prepw: weights row-major fp32 -> B-frag tf32 ----
        int gid = (b - PB_CONV) * 256 + t;   // 0..20479
        int m = gid >> 12, g = gid & 4095;
        int w = g * 4;
        int lane = w & 31, reg = (w >> 5) & 1, ntile = (w >> 6) & 15, k8 = w >> 10;
        int n = ntile * 8 + (lane >> 2);
        int k = k8 * 8 + reg * 4;
        float4 v = make_float4(0.f, 0.f, 0.f, 0.f);
        float* dst;
        switch (m) {
            case 0: v = __ldg((const float4*)(w1l + (size_t)n * C_DIM + k)); dst = w1lF; break;
            case 1: v = __ldg((const float4*)(w1r + (size_t)n * C_DIM + k)); dst = w1rF; break;
            case 2: v = __ldg((const float4*)(w2l + (size_t)n * C_DIM + k)); dst = w2lF; break;
            case 3: v = __ldg((const float4*)(w2r + (size_t)n * C_DIM + k)); dst = w2rF; break;
            default:
                if (n < 64)       v = __ldg((const float4*)(wa + (size_t)n * C_DIM + k));
                else if (n == 64) v = __ldg((const float4*)(wc + k));
                dst = headBF; break;
        }
        *(uint4*)(dst + w) = make_uint4(f2tf(v.x), f2tf(v.y), f2tf(v.z), f2tf(v.w));
    } else {
        // ---- fill: bucketed CSR build, inline int64/int32 detection ----
        __shared__ int s_is64;
        {
            bool ok = true;
            if (t < 16) {
                int lo = ((const int*)ei)[2 * t];
                int hi = ((const int*)ei)[2 * t + 1];
                ok = (hi == 0) && ((unsigned)lo < (unsigned)N_NODES);
            }
            unsigned m = __ballot_sync(0xffffffffu, ok);
            if (t == 0) s_is64 = (m == 0xffffffffu) ? 1 : 0;
        }
        __syncthreads();
        int is64 = s_is64;
        int e = (b - PB_W) * 256 + t;        // 0..639999 exactly
        int src, dst;
        if (is64) {
            src = (int)((const long long*)ei)[e];
            dst = (int)((const long long*)ei)[N_EDGES + e];
        } else {
            src = ((const int*)ei)[e];
            dst = ((const int*)ei)[N_EDGES + e];
        }
        int pos = atomicAdd(&cursor[dst], 1);
        if (pos < BUCKET) csr[dst * BUCKET + pos] = src;
    }
}

// ---------------- mean aggregation: warp per node, MLP=8, pipelined index loads ----
// Index prefetch is UNCONDITIONAL with clamped bucket offsets (bucket is a fixed
// 16 x int4 region, always readable). Loop invariant: entering an iteration or
// tail at position i, ia/ib hold bucket positions i..i+7. Clamped (duplicate)
// loads are only consumed at positions >= e, i.e. never.
__global__ __launch_bounds__(256) void gather_kernel(int* __restrict__ cursor,
                                                     const int* __restrict__ csr,
                                                     const __half* __restrict__ xh,
                                                     float* __restrict__ meanF,
                                                     int zero_cursor) {
    int gt = blockIdx.x * blockDim.x + threadIdx.x;
    int n = gt >> 5;
    if (n >= N_NODES) return;
    int lane = gt & 31;
    const int4* bkt4 = (const int4*)(csr + n * BUCKET);   // 256B-aligned buckets
    // issue first index group BEFORE deg is known (concurrent L2 trips)
    int4 ia = __ldg(&bkt4[0]);
    int4 ib = __ldg(&bkt4[1]);
    int deg = __ldg(&cursor[n]);
    int e = (deg < BUCKET) ? deg : BUCKET;
    if (zero_cursor && lane == 0) cursor[n] = 0;   // restore for next replay's fill
    float4 acc = make_float4(0.f, 0.f, 0.f, 0.f);
    int i = 0;
    for (; i + 8 <= e; i += 8) {
        // unconditional prefetch of positions i+8..i+15 (clamped to bucket end)
        int pa = (i >> 2) + 2, pb = (i >> 2) + 3;
        if (pa > 15) pa = 15;
        if (pb > 15) pb = 15;
        int4 na = __ldg(&bkt4[pa]);
        int4 nb = __ldg(&bkt4[pb]);
        // 8 independent row loads in flight (MLP=8)
        uint2 u0 = __ldg((const uint2*)(xh + (size_t)ia.x * C_DIM) + lane);
        uint2 u1 = __ldg((const uint2*)(xh + (size_t)ia.y * C_DIM) + lane);
        uint2 u2 = __ldg((const uint2*)(xh + (size_t)ia.z * C_DIM) + lane);
        uint2 u3 = __ldg((const uint2*)(xh + (size_t)ia.w * C_DIM) + lane);
        uint2 u4 = __ldg((const uint2*)(xh + (size_t)ib.x * C_DIM) + lane);
        uint2 u5 = __ldg((const uint2*)(xh + (size_t)ib.y * C_DIM) + lane);
        uint2 u6 = __ldg((const uint2*)(xh + (size_t)ib.z * C_DIM) + lane);
        uint2 u7 = __ldg((const uint2*)(xh + (size_t)ib.w * C_DIM) + lane);
        float2 p;
        p = __half22float2(*(__half2*)&u0.x); acc.x += p.x; acc.y += p.y;
        p = __half22float2(*(__half2*)&u0.y); acc.z += p.x; acc.w += p.y;
        p = __half22float2(*(__half2*)&u1.x); acc.x += p.x; acc.y += p.y;
        p = __half22float2(*(__half2*)&u1.y); acc.z += p.x; acc.w += p.y;
        p = __half22float2(*(__half2*)&u2.x); acc.x += p.x; acc.y += p.y;
        p = __half22float2(*(__half2*)&u2.y); acc.z += p.x; acc.w += p.y;
        p = __half22float2(*(__half2*)&u3.x); acc.x += p.x; acc.y += p.y;
        p = __half22float2(*(__half2*)&u3.y); acc.z += p.x; acc.w += p.y;
        p = __half22float2(*(__half2*)&u4.x); acc.x += p.x; acc.y += p.y;
        p = __half22float2(*(__half2*)&u4.y); acc.z += p.x; acc.w += p.y;
        p = __half22float2(*(__half2*)&u5.x); acc.x += p.x; acc.y += p.y;
        p = __half22float2(*(__half2*)&u5.y); acc.z += p.x; acc.w += p.y;
        p = __half22float2(*(__half2*)&u6.x); acc.x += p.x; acc.y += p.y;
        p = __half22float2(*(__half2*)&u6.y); acc.z += p.x; acc.w += p.y;
        p = __half22float2(*(__half2*)&u7.x); acc.x += p.x; acc.y += p.y;
        p = __half22float2(*(__half2*)&u7.y); acc.z += p.x; acc.w += p.y;
        ia = na; ib = nb;
    }
    if (i + 4 <= e) {
        // ia holds positions i..i+3 (loop invariant)
        uint2 u0 = __ldg((const uint2*)(xh + (size_t)ia.x * C_DIM) + lane);
        uint2 u1 = __ldg((const uint2*)(xh + (size_t)ia.y * C_DIM) + lane);
        uint2 u2 = __ldg((const uint2*)(xh + (size_t)ia.z * C_DIM) + lane);
        uint2 u3 = __ldg((const uint2*)(xh + (size_t)ia.w * C_DIM) + lane);
        float2 p;
        p = __half22float2(*(__half2*)&u0.x); acc.x += p.x; acc.y += p.y;
        p = __half22float2(*(__half2*)&u0.y); acc.z += p.x; acc.w += p.y;
        p = __half22float2(*(__half2*)&u1.x); acc.x += p.x; acc.y += p.y;
        p = __half22float2(*(__half2*)&u1.y); acc.z += p.x; acc.w += p.y;
        p = __half22float2(*(__half2*)&u2.x); acc.x += p.x; acc.y += p.y;
        p = __half22float2(*(__half2*)&u2.y); acc.z += p.x; acc.w += p.y;
        p = __half22float2(*(__half2*)&u3.x); acc.x += p.x; acc.y += p.y;
        p = __half22float2(*(__half2*)&u3.y); acc.z += p.x; acc.w += p.y;
        ia = ib;   // positions i+4..i+7
        i += 4;
    }
    // scalar tail (<4 edges) — ia holds positions i..i+3
    {
        const int tail[4] = {ia.x, ia.y, ia.z, ia.w};
        int tcount = e - i;
#pragma unroll
        for (int j = 0; j < 3; j++) {
            if (j < tcount) {
                uint2 u0 = __ldg((const uint2*)(xh + (size_t)tail[j] * C_DIM) + lane);
                float2 p;
                p = __half22float2(*(__half2*)&u0.x); acc.x += p.x; acc.y += p.y;
                p = __half22float2(*(__half2*)&u0.y); acc.z += p.x; acc.w += p.y;
            }
        }
    }
    float inv = 1.0f / fmaxf((float)deg, 1.0f);
    // frag write: lane holds k = 4*lane..4*lane+3 for row r = n&127
    int bm = n >> 7, r = n & 127;
    int k8 = lane >> 1;
    int reg = ((r >> 3) & 1) | ((lane & 1) << 1);
    int tile = (r >> 4) & 7;
    size_t base = (size_t)bm * SLAB + (((k8 * 8 + tile) * 4 + reg) * 32) + ((r & 7) * 4);
    *(uint4*)(meanF + base) = make_uint4(f2tf(acc.x * inv), f2tf(acc.y * inv),
                                         f2tf(acc.z * inv), f2tf(acc.w * inv));
}

// ---------------- pipelined tf32 SAGE GEMM + fused epilogue conversion ----------
__global__ __launch_bounds__(256, 2) void sage_pipe_kernel(
    const float* __restrict__ meanF, const float* __restrict__ xF,
    const float* __restrict__ wlF, const float* __restrict__ wrF,
    const float* __restrict__ bl,
    __half* __restrict__ out_h,      // fp16 row-major output (may be null)
    float* __restrict__ outF) {      // A-frag tf32 output slab array
    extern __shared__ float smem[];
    uint32_t sbase = smem_u32(smem);
    const int t = threadIdx.x;
    const int wid = t >> 5, lid = t & 31;
    const int wm = wid >> 2, wn = wid & 3;
    const int bm = blockIdx.x;
    const int node0 = bm * 128;

    const float* Aslab0 = meanF + (size_t)bm * SLAB;
    const float* Aslab1 = xF + (size_t)bm * SLAB;

    float acc[4][4][4];
#pragma unroll
    for (int i = 0; i < 4; i++)
#pragma unroll
        for (int j = 0; j < 4; j++) {
            acc[i][j][0] = 0.f; acc[i][j][1] = 0.f; acc[i][j][2] = 0.f; acc[i][j][3] = 0.f;
        }

    {
#pragma unroll
        for (int s = 0; s < 4; s++) {
            int o = (t + s * 256) * 4;
            cp16(sbase + o * 4, Aslab0 + o);
            cp16(sbase + 16384 + o * 4, wlF + o);
        }
        CP_COMMIT();
    }

#pragma unroll 1
    for (int ch = 0; ch < 8; ch++) {
        if (ch < 7) {
            int nc = ch + 1;
            const float* A = ((nc < 4) ? Aslab0 : Aslab1) + (nc & 3) * 4096;
            const float* B = ((nc < 4) ? wlF : wrF) + (nc & 3) * 4096;
            uint32_t d = sbase + (uint32_t)((nc & 1) * 32768);
#pragma unroll
            for (int s = 0; s < 4; s++) {
                int o = (t + s * 256) * 4;
                cp16(d + o * 4, A + o);
                cp16(d + 16384 + o * 4, B + o);
            }
            CP_COMMIT();
            CP_WAIT1();
        } else {
            CP_WAIT0();
        }
        __syncthreads();
        const uint32_t* sA = (const uint32_t*)smem + (ch & 1) * 8192;
        const uint32_t* sB = sA + 4096;
        mma_chunk(sA, sB, acc, wm, wn, lid);
        __syncthreads();
    }

    // ---- fused epilogue: stage relu(acc+bias) into smem [128][132] ----
    const int lrow = wm * 64 + (lid >> 2);
    const int cbase = wn * 32 + (lid & 3) * 2;
#pragma unroll
    for (int j = 0; j < 4; j++) {
        int col = cbase + j * 8;
        float b0 = __ldg(&bl[col]), b1 = __ldg(&bl[col + 1]);
#pragma unroll
        for (int i = 0; i < 4; i++) {
            int r0 = lrow + i * 16;
            smem[r0 * 132 + col]     = fmaxf(acc[i][j][0] + b0, 0.f);
            smem[r0 * 132 + col + 1] = fmaxf(acc[i][j][1] + b1, 0.f);
            smem[(r0 + 8) * 132 + col]     = fmaxf(acc[i][j][2] + b0, 0.f);
            smem[(r0 + 8) * 132 + col + 1] = fmaxf(acc[i][j][3] + b1, 0.f);
        }
    }
    __syncthreads();

    if (out_h) {
#pragma unroll
        for (int i = 0; i < 16; i++) {
            int idx = t + i * 256;
            int row = idx >> 5, c4 = (idx & 31) * 4;
            int node = node0 + row;
            if (node < N_NODES) {
                const float* p = &smem[row * 132 + c4];
                *(uint2*)(out_h + (size_t)node * C_DIM + c4) =
                    pack_half4(p[0], p[1], p[2], p[3]);
            }
        }
    }

    float* slab = outF + (size_t)bm * SLAB;
#pragma unroll
    for (int i = 0; i < 16; i++) {
        int w = (t + i * 256) * 4;
        int lane = w & 31, reg = (w >> 5) & 3, tile = (w >> 7) & 7, k8c = w >> 10;
        int row = tile * 16 + (reg & 1) * 8 + (lane >> 2);
        int kb = k8c * 8 + ((reg >> 1) & 1) * 4;
        float4 v = *(const float4*)&smem[row * 132 + kb];
        *(uint4*)(slab + w) = make_uint4(f2tf(v.x), f2tf(v.y), f2tf(v.z), f2tf(v.w));
    }
}

// ---------------- pipelined head: logits (cols 0-63) + value (col 64) ----------------
__global__ __launch_bounds__(256, 2) void head_pipe_kernel(
    const float* __restrict__ hF, const float* __restrict__ headBF,
    const float* __restrict__ ba, const float* __restrict__ bc,
    float* __restrict__ out) {
    extern __shared__ float smem[];
    uint32_t sbase = smem_u32(smem);
    const int t = threadIdx.x;
    const int wid = t >> 5, lid = t & 31;
    const int wm = wid >> 2, wn = wid & 3;
    const int bm = blockIdx.x;
    const int node0 = bm * 128;
    const float* Aslab = hF + (size_t)bm * SLAB;

    float acc[4][4][4];
#pragma unroll
    for (int i = 0; i < 4; i++)
#pragma unroll
        for (int j = 0; j < 4; j++) {
            acc[i][j][0] = 0.f; acc[i][j][1] = 0.f; acc[i][j][2] = 0.f; acc[i][j][3] = 0.f;
        }

    {
#pragma unroll
        for (int s = 0; s < 4; s++) {
            int o = (t + s * 256) * 4;
            cp16(sbase + o * 4, Aslab + o);
            cp16(sbase + 16384 + o * 4, headBF + o);
        }
        CP_COMMIT();
    }
#pragma unroll 1
    for (int ch = 0; ch < 4; ch++) {
        if (ch < 3) {
            int nc = ch + 1;
            uint32_t d = sbase + (uint32_t)((nc & 1) * 32768);
#pragma unroll
            for (int s = 0; s < 4; s++) {
                int o = (t + s * 256) * 4;
                cp16(d + o * 4, Aslab + nc * 4096 + o);
                cp16(d + 16384 + o * 4, headBF + nc * 4096 + o);
            }
            CP_COMMIT();
            CP_WAIT1();
        } else {
            CP_WAIT0();
        }
        __syncthreads();
        const uint32_t* sA = (const uint32_t*)smem + (ch & 1) * 8192;
        const uint32_t* sB = sA + 4096;
        mma_chunk(sA, sB, acc, wm, wn, lid);
        __syncthreads();
    }

    const int rbase = node0 + wm * 64 + (lid >> 2);
    const int cbase = wn * 32 + (lid & 3) * 2;
#pragma unroll
    for (int j = 0; j < 4; j++) {
        int col = cbase + j * 8;
        if (col < 64) {
            float b0 = __ldg(&ba[col]), b1 = __ldg(&ba[col + 1]);
#pragma unroll
            for (int i = 0; i < 4; i++) {
                int n0 = rbase + i * 16;
                if (n0 < N_NODES)
                    *(float2*)(out + (size_t)n0 * OUT_CH + col) =
                        make_float2(acc[i][j][0] + b0, acc[i][j][1] + b1);
                int n1 = n0 + 8;
                if (n1 < N_NODES)
                    *(float2*)(out + (size_t)n1 * OUT_CH + col) =
                        make_float2(acc[i][j][2] + b0, acc[i][j][3] + b1);
            }
        } else if (col == 64) {
            float b0 = __ldg(&bc[0]);
#pragma unroll
            for (int i = 0; i < 4; i++) {
                int n0 = rbase + i * 16;
                if (n0 < N_NODES)
                    out[(size_t)N_NODES * OUT_CH + n0] = acc[i][j][0] + b0;
                int n1 = n0 + 8;
                if (n1 < N_NODES)
                    out[(size_t)N_NODES * OUT_CH + n1] = acc[i][j][2] + b0;
            }
        }
    }
}

// ---------------- launch (single stream, 6 launches, no allocations) ------
extern "C" void kernel_launch(void* const* d_in, const int* in_sizes, int n_in,
                              void* d_out, int out_size) {
    const float* x   = (const float*)d_in[0];
    const void*  ei  = d_in[1];
    const float* w1l = (const float*)d_in[2];
    const float* b1l = (const float*)d_in[3];
    const float* w1r = (const float*)d_in[4];
    const float* w2l = (const float*)d_in[5];
    const float* b2l = (const float*)d_in[6];
    const float* w2r = (const float*)d_in[7];
    const float* wa  = (const float*)d_in[8];
    const float* ba  = (const float*)d_in[9];
    const float* wc  = (const float*)d_in[10];
    const float* bc  = (const float*)d_in[11];
    float* out = (float*)d_out;

    float *meanF, *xF, *h1F, *h2F, *w1lF, *w1rF, *w2lF, *w2rF, *headBF;
    __half *xH, *h1H;
    int *cursor, *csr;
    cudaGetSymbolAddress((void**)&xH,     g_xH);
    cudaGetSymbolAddress((void**)&h1H,    g_h1H);
    cudaGetSymbolAddress((void**)&meanF,  g_meanF);
    cudaGetSymbolAddress((void**)&xF,     g_xF);
    cudaGetSymbolAddress((void**)&h1F,    g_h1F);
    cudaGetSymbolAddress((void**)&h2F,    g_h2F);
    cudaGetSymbolAddress((void**)&w1lF,   g_w1lF);
    cudaGetSymbolAddress((void**)&w1rF,   g_w1rF);
    cudaGetSymbolAddress((void**)&w2lF,   g_w2lF);
    cudaGetSymbolAddress((void**)&w2rF,   g_w2rF);
    cudaGetSymbolAddress((void**)&headBF, g_headBF);
    cudaGetSymbolAddress((void**)&cursor, g_cursor);
    cudaGetSymbolAddress((void**)&csr,    g_csr);

    const int SAGE_SMEM = 128 * 132 * 4;  // 67584 >= 64KB pipeline needs
    const int HEAD_SMEM = 65536;
    cudaFuncSetAttribute(sage_pipe_kernel, cudaFuncAttributeMaxDynamicSharedMemorySize, SAGE_SMEM);
    cudaFuncSetAttribute(head_pipe_kernel, cudaFuncAttributeMaxDynamicSharedMemorySize, HEAD_SMEM);

    // ---- all prep in one wide kernel (convertA | prepw | fill) ----
    prep_all_kernel<<<PB_FILL, 256>>>(x, ei, w1l, w1r, w2l, w2r, wa, wc,
                                      xF, xH, w1lF, w1rF, w2lF, w2rF, headBF,
                                      cursor, csr);

    const int gather_blocks = (N_NODES * 32) / 256;  // 5000

    // ---- layer 1 ----
    gather_kernel<<<gather_blocks, 256>>>(cursor, csr, xH, meanF, 0);
    sage_pipe_kernel<<<NBLK, 256, SAGE_SMEM>>>(meanF, xF, w1lF, w1rF, b1l, h1H, h1F);

    // ---- layer 2 (last cursor reader restores it to zero for next replay) ----
    gather_kernel<<<gather_blocks, 256>>>(cursor, csr, h1H, meanF, 1);
    sage_pipe_kernel<<<NBLK, 256, SAGE_SMEM>>>(meanF, h1F, w2lF, w2rF, b2l, nullptr, h2F);

    // ---- heads ----
    head_pipe_kernel<<<NBLK, 256, HEAD_SMEM>>>(h2F, headBF, ba, bc, out);
}

// round 15
// speedup vs baseline: 1.4868x; 1.0355x over previous
#include <cuda_runtime.h>
#include <cuda_fp16.h>
#include <cstdint>

#define N_NODES 40000
#define N_EDGES 640000
#define C_DIM   128
#define OUT_CH  64
#define BUCKET  64
#define NBLK    313          // ceil(40000/128)
#define SLAB    16384        // words per 128-row A-frag slab (128x128)

// prep_all block partition
#define PB_CONV 1252                     // NBLK*4 convertA blocks
#define PB_W    (PB_CONV + 80)           // 80 prepw blocks
#define PB_FILL (PB_W + 2500)            // 2500 fill blocks (640000/256)

// ---------------- device scratch (no allocations allowed) ----------------
__device__ __half g_xH[N_NODES * C_DIM];    // fp16 copy of x for gather
__device__ __half g_h1H[N_NODES * C_DIM];   // fp16 copy of h1 for gather
__device__ float g_meanF[NBLK * SLAB];
__device__ float g_xF[NBLK * SLAB];
__device__ float g_h1F[NBLK * SLAB];
__device__ float g_w1lF[SLAB], g_w1rF[SLAB], g_w2lF[SLAB], g_w2rF[SLAB], g_headBF[SLAB];
__device__ int   g_cursor[N_NODES];   // zero-initialized; self-restored each run
__device__ int   g_csr[N_NODES * BUCKET];

// ---------------- helpers ----------------
__device__ __forceinline__ uint32_t f2tf(float v) {
    uint32_t r; asm("cvt.rna.tf32.f32 %0, %1;" : "=r"(r) : "f"(v)); return r;
}
__device__ __forceinline__ uint32_t smem_u32(const void* p) {
    uint32_t a;
    asm("{ .reg .u64 t; cvta.to.shared.u64 t, %1; cvt.u32.u64 %0, t; }" : "=r"(a) : "l"(p));
    return a;
}
__device__ __forceinline__ void cp16(uint32_t dst, const void* src) {
    asm volatile("cp.async.ca.shared.global [%0], [%1], 16;" :: "r"(dst), "l"(src));
}
#define CP_COMMIT() asm volatile("cp.async.commit_group;" ::: "memory")
#define CP_WAIT1()  asm volatile("cp.async.wait_group 1;" ::: "memory")
#define CP_WAIT0()  asm volatile("cp.async.wait_group 0;" ::: "memory")

__device__ __forceinline__ uint2 pack_half4(float a, float b, float c, float d) {
    __half2 h01 = __floats2half2_rn(a, b);
    __half2 h23 = __floats2half2_rn(c, d);
    uint2 p;
    p.x = *(uint32_t*)&h01;
    p.y = *(uint32_t*)&h23;
    return p;
}

__device__ __forceinline__ void mma_tf32(float& d0, float& d1, float& d2, float& d3,
                                         uint32_t a0, uint32_t a1, uint32_t a2, uint32_t a3,
                                         uint32_t b0, uint32_t b1) {
    asm volatile(
        "mma.sync.aligned.m16n8k8.row.col.f32.tf32.tf32.f32 "
        "{%0,%1,%2,%3}, {%4,%5,%6,%7}, {%8,%9}, {%0,%1,%2,%3};"
        : "+f"(d0), "+f"(d1), "+f"(d2), "+f"(d3)
        : "r"(a0), "r"(a1), "r"(a2), "r"(a3), "r"(b0), "r"(b1));
}

// mma over one staged 128x128x32 chunk; warp tile 64 nodes x 32 outs
// A chunk layout: [k8=4][m_tile=8][reg=4][lane=32]; B: [k8=4][n_tile=16][reg=2][lane=32]
__device__ __forceinline__ void mma_chunk(const uint32_t* sA, const uint32_t* sB,
                                          float acc[4][4][4], int wm, int wn, int lid) {
#pragma unroll
    for (int k8 = 0; k8 < 4; k8++) {
        uint32_t a[4][4], b[4][2];
#pragma unroll
        for (int i = 0; i < 4; i++) {
            uint32_t base = ((k8 * 8 + (wm * 4 + i)) * 4) * 32 + lid;
            a[i][0] = sA[base];      a[i][1] = sA[base + 32];
            a[i][2] = sA[base + 64]; a[i][3] = sA[base + 96];
        }
#pragma unroll
        for (int j = 0; j < 4; j++) {
            uint32_t base = ((k8 * 16 + (wn * 4 + j)) * 2) * 32 + lid;
            b[j][0] = sB[base]; b[j][1] = sB[base + 32];
        }
#pragma unroll
        for (int i = 0; i < 4; i++)
#pragma unroll
            for (int j = 0; j < 4; j++)
                mma_tf32(acc[i][j][0], acc[i][j][1], acc[i][j][2], acc[i][j][3],
                         a[i][0], a[i][1], a[i][2], a[i][3], b[j][0], b[j][1]);
    }
}

// shared sage mainloop + epilogue staging: computes relu([mean|x]@[wl;wr]^T + bl)
// for 128 nodes into smem as [128][132] fp32. Caller provides smem (>= 67584 B).
__device__ __forceinline__ void sage_mainloop(
    float* smem, uint32_t sbase,
    const float* Aslab0, const float* Aslab1,
    const float* wlF, const float* wrF, const float* bl,
    int t, int wid, int lid) {
    const int wm = wid >> 2, wn = wid & 3;
    float acc[4][4][4];
#pragma unroll
    for (int i = 0; i < 4; i++)
#pragma unroll
        for (int j = 0; j < 4; j++) {
            acc[i][j][0] = 0.f; acc[i][j][1] = 0.f; acc[i][j][2] = 0.f; acc[i][j][3] = 0.f;
        }

    {
#pragma unroll
        for (int s = 0; s < 4; s++) {
            int o = (t + s * 256) * 4;
            cp16(sbase + o * 4, Aslab0 + o);
            cp16(sbase + 16384 + o * 4, wlF + o);
        }
        CP_COMMIT();
    }

#pragma unroll 1
    for (int ch = 0; ch < 8; ch++) {
        if (ch < 7) {
            int nc = ch + 1;
            const float* A = ((nc < 4) ? Aslab0 : Aslab1) + (nc & 3) * 4096;
            const float* B = ((nc < 4) ? wlF : wrF) + (nc & 3) * 4096;
            uint32_t d = sbase + (uint32_t)((nc & 1) * 32768);
#pragma unroll
            for (int s = 0; s < 4; s++) {
                int o = (t + s * 256) * 4;
                cp16(d + o * 4, A + o);
                cp16(d + 16384 + o * 4, B + o);
            }
            CP_COMMIT();
            CP_WAIT1();
        } else {
            CP_WAIT0();
        }
        __syncthreads();
        const uint32_t* sA = (const uint32_t*)smem + (ch & 1) * 8192;
        const uint32_t* sB = sA + 4096;
        mma_chunk(sA, sB, acc, wm, wn, lid);
        __syncthreads();
    }

    // stage relu(acc+bias) into smem [128][132]
    const int lrow = wm * 64 + (lid >> 2);
    const int cbase = wn * 32 + (lid & 3) * 2;
#pragma unroll
    for (int j = 0; j < 4; j++) {
        int col = cbase + j * 8;
        float b0 = __ldg(&bl[col]), b1 = __ldg(&bl[col + 1]);
#pragma unroll
        for (int i = 0; i < 4; i++) {
            int r0 = lrow + i * 16;
            smem[r0 * 132 + col]     = fmaxf(acc[i][j][0] + b0, 0.f);
            smem[r0 * 132 + col + 1] = fmaxf(acc[i][j][1] + b1, 0.f);
            smem[(r0 + 8) * 132 + col]     = fmaxf(acc[i][j][2] + b0, 0.f);
            smem[(r0 + 8) * 132 + col + 1] = fmaxf(acc[i][j][3] + b1, 0.f);
        }
    }
    __syncthreads();
}

// ================= fused prep: convertA + prepw + fill in ONE kernel =================
__global__ __launch_bounds__(256) void prep_all_kernel(
    const float* __restrict__ x, const void* __restrict__ ei,
    const float* __restrict__ w1l, const float* __restrict__ w1r,
    const float* __restrict__ w2l, const float* __restrict__ w2r,
    const float* __restrict__ wa, const float* __restrict__ wc,
    float* __restrict__ xF, __half* __restrict__ xH,
    float* __restrict__ w1lF, float* __restrict__ w1rF,
    float* __restrict__ w2lF, float* __restrict__ w2rF,
    float* __restrict__ headBF,
    int* __restrict__ cursor, int* __restrict__ csr) {
    const int b = blockIdx.x;
    const int t = threadIdx.x;

    if (b < PB_CONV) {
        // ---- convertA: x row-major fp32 -> A-frag tf32 slab + fp16 copy ----
        __shared__ __align__(16) float s[128][36];
        const int bm = b >> 2;
        const int ch = b & 3;
        const int node0 = bm * 128;
        float* slab = xF + (size_t)bm * SLAB;
#pragma unroll
        for (int i = 0; i < 4; i++) {
            int idx = t + i * 256;
            int row = idx >> 3, k4 = (idx & 7) * 4;
            int node = node0 + row;
            bool valid = (node < N_NODES);
            if (!valid) node = N_NODES - 1;
            float4 v = __ldg((const float4*)(x + (size_t)node * C_DIM + ch * 32 + k4));
            *(float4*)&s[row][k4] = v;
            if (valid)
                *(uint2*)(xH + (size_t)node * C_DIM + ch * 32 + k4) =
                    pack_half4(v.x, v.y, v.z, v.w);
        }
        __syncthreads();
#pragma unroll
        for (int i = 0; i < 4; i++) {
            int w = (t + i * 256) * 4;
            int lane = w & 31, reg = (w >> 5) & 3, tile = (w >> 7) & 7, k8 = w >> 10;
            int row = tile * 16 + (reg & 1) * 8 + (lane >> 2);
            int kb = k8 * 8 + ((reg >> 1) & 1) * 4;
            float4 v = *(const float4*)&s[row][kb];
            *(uint4*)(slab + ch * 4096 + w) =
                make_uint4(f2tf(v.x), f2tf(v.y), f2tf(v.z), f2tf(v.w));
        }
    } else if (b < PB_W) {
        // ---- prepw: weights row-major fp32 -> B-frag tf32 ----
        int gid = (b - PB_CONV) * 256 + t;   // 0..20479
        int m = gid >> 12, g = gid & 4095;
        int w = g * 4;
        int lane = w & 31, reg = (w >> 5) & 1, ntile = (w >> 6) & 15, k8 = w >> 10;
        int n = ntile * 8 + (lane >> 2);
        int k = k8 * 8 + reg * 4;
        float4 v = make_float4(0.f, 0.f, 0.f, 0.f);
        float* dst;
        switch (m) {
            case 0: v = __ldg((const float4*)(w1l + (size_t)n * C_DIM + k)); dst = w1lF; break;
            case 1: v = __ldg((const float4*)(w1r + (size_t)n * C_DIM + k)); dst = w1rF; break;
            case 2: v = __ldg((const float4*)(w2l + (size_t)n * C_DIM + k)); dst = w2lF; break;
            case 3: v = __ldg((const float4*)(w2r + (size_t)n * C_DIM + k)); dst = w2rF; break;
            default:
                if (n < 64)       v = __ldg((const float4*)(wa + (size_t)n * C_DIM + k));
                else if (n == 64) v = __ldg((const float4*)(wc + k));
                dst = headBF; break;
        }
        *(uint4*)(dst + w) = make_uint4(f2tf(v.x), f2tf(v.y), f2tf(v.z), f2tf(v.w));
    } else {
        // ---- fill: bucketed CSR build, inline int64/int32 detection ----
        __shared__ int s_is64;
        {
            bool ok = true;
            if (t < 16) {
                int lo = ((const int*)ei)[2 * t];
                int hi = ((const int*)ei)[2 * t + 1];
                ok = (hi == 0) && ((unsigned)lo < (unsigned)N_NODES);
            }
            unsigned m = __ballot_sync(0xffffffffu, ok);
            if (t == 0) s_is64 = (m == 0xffffffffu) ? 1 : 0;
        }
        __syncthreads();
        int is64 = s_is64;
        int e = (b - PB_W) * 256 + t;        // 0..639999 exactly
        int src, dst;
        if (is64) {
            src = (int)((const long long*)ei)[e];
            dst = (int)((const long long*)ei)[N_EDGES + e];
        } else {
            src = ((const int*)ei)[e];
            dst = ((const int*)ei)[N_EDGES + e];
        }
        int pos = atomicAdd(&cursor[dst], 1);
        if (pos < BUCKET) csr[dst * BUCKET + pos] = src;
    }
}

// ---------------- mean aggregation: warp per node, MLP=8, pipelined index loads ----
__global__ __launch_bounds__(256) void gather_kernel(int* __restrict__ cursor,
                                                     const int* __restrict__ csr,
                                                     const __half* __restrict__ xh,
                                                     float* __restrict__ meanF,
                                                     int zero_cursor) {
    int gt = blockIdx.x * blockDim.x + threadIdx.x;
    int n = gt >> 5;
    if (n >= N_NODES) return;
    int lane = gt & 31;
    const int4* bkt4 = (const int4*)(csr + n * BUCKET);   // 256B-aligned buckets
    // issue first index group BEFORE deg is known (concurrent L2 trips)
    int4 ia = __ldg(&bkt4[0]);
    int4 ib = __ldg(&bkt4[1]);
    int deg = __ldg(&cursor[n]);
    int e = (deg < BUCKET) ? deg : BUCKET;
    if (zero_cursor && lane == 0) cursor[n] = 0;   // restore for next replay's fill
    float4 acc = make_float4(0.f, 0.f, 0.f, 0.f);
    int i = 0;
    for (; i + 8 <= e; i += 8) {
        // unconditional prefetch of positions i+8..i+15 (clamped to bucket end)
        int pa = (i >> 2) + 2, pb = (i >> 2) + 3;
        if (pa > 15) pa = 15;
        if (pb > 15) pb = 15;
        int4 na = __ldg(&bkt4[pa]);
        int4 nb = __ldg(&bkt4[pb]);
        uint2 u0 = __ldg((const uint2*)(xh + (size_t)ia.x * C_DIM) + lane);
        uint2 u1 = __ldg((const uint2*)(xh + (size_t)ia.y * C_DIM) + lane);
        uint2 u2 = __ldg((const uint2*)(xh + (size_t)ia.z * C_DIM) + lane);
        uint2 u3 = __ldg((const uint2*)(xh + (size_t)ia.w * C_DIM) + lane);
        uint2 u4 = __ldg((const uint2*)(xh + (size_t)ib.x * C_DIM) + lane);
        uint2 u5 = __ldg((const uint2*)(xh + (size_t)ib.y * C_DIM) + lane);
        uint2 u6 = __ldg((const uint2*)(xh + (size_t)ib.z * C_DIM) + lane);
        uint2 u7 = __ldg((const uint2*)(xh + (size_t)ib.w * C_DIM) + lane);
        float2 p;
        p = __half22float2(*(__half2*)&u0.x); acc.x += p.x; acc.y += p.y;
        p = __half22float2(*(__half2*)&u0.y); acc.z += p.x; acc.w += p.y;
        p = __half22float2(*(__half2*)&u1.x); acc.x += p.x; acc.y += p.y;
        p = __half22float2(*(__half2*)&u1.y); acc.z += p.x; acc.w += p.y;
        p = __half22float2(*(__half2*)&u2.x); acc.x += p.x; acc.y += p.y;
        p = __half22float2(*(__half2*)&u2.y); acc.z += p.x; acc.w += p.y;
        p = __half22float2(*(__half2*)&u3.x); acc.x += p.x; acc.y += p.y;
        p = __half22float2(*(__half2*)&u3.y); acc.z += p.x; acc.w += p.y;
        p = __half22float2(*(__half2*)&u4.x); acc.x += p.x; acc.y += p.y;
        p = __half22float2(*(__half2*)&u4.y); acc.z += p.x; acc.w += p.y;
        p = __half22float2(*(__half2*)&u5.x); acc.x += p.x; acc.y += p.y;
        p = __half22float2(*(__half2*)&u5.y); acc.z += p.x; acc.w += p.y;
        p = __half22float2(*(__half2*)&u6.x); acc.x += p.x; acc.y += p.y;
        p = __half22float2(*(__half2*)&u6.y); acc.z += p.x; acc.w += p.y;
        p = __half22float2(*(__half2*)&u7.x); acc.x += p.x; acc.y += p.y;
        p = __half22float2(*(__half2*)&u7.y); acc.z += p.x; acc.w += p.y;
        ia = na; ib = nb;
    }
    if (i + 4 <= e) {
        uint2 u0 = __ldg((const uint2*)(xh + (size_t)ia.x * C_DIM) + lane);
        uint2 u1 = __ldg((const uint2*)(xh + (size_t)ia.y * C_DIM) + lane);
        uint2 u2 = __ldg((const uint2*)(xh + (size_t)ia.z * C_DIM) + lane);
        uint2 u3 = __ldg((const uint2*)(xh + (size_t)ia.w * C_DIM) + lane);
        float2 p;
        p = __half22float2(*(__half2*)&u0.x); acc.x += p.x; acc.y += p.y;
        p = __half22float2(*(__half2*)&u0.y); acc.z += p.x; acc.w += p.y;
        p = __half22float2(*(__half2*)&u1.x); acc.x += p.x; acc.y += p.y;
        p = __half22float2(*(__half2*)&u1.y); acc.z += p.x; acc.w += p.y;
        p = __half22float2(*(__half2*)&u2.x); acc.x += p.x; acc.y += p.y;
        p = __half22float2(*(__half2*)&u2.y); acc.z += p.x; acc.w += p.y;
        p = __half22float2(*(__half2*)&u3.x); acc.x += p.x; acc.y += p.y;
        p = __half22float2(*(__half2*)&u3.y); acc.z += p.x; acc.w += p.y;
        ia = ib;
        i += 4;
    }
    {
        const int tail[4] = {ia.x, ia.y, ia.z, ia.w};
        int tcount = e - i;
#pragma unroll
        for (int j = 0; j < 3; j++) {
            if (j < tcount) {
                uint2 u0 = __ldg((const uint2*)(xh + (size_t)tail[j] * C_DIM) + lane);
                float2 p;
                p = __half22float2(*(__half2*)&u0.x); acc.x += p.x; acc.y += p.y;
                p = __half22float2(*(__half2*)&u0.y); acc.z += p.x; acc.w += p.y;
            }
        }
    }
    float inv = 1.0f / fmaxf((float)deg, 1.0f);
    int bm = n >> 7, r = n & 127;
    int k8 = lane >> 1;
    int reg = ((r >> 3) & 1) | ((lane & 1) << 1);
    int tile = (r >> 4) & 7;
    size_t base = (size_t)bm * SLAB + (((k8 * 8 + tile) * 4 + reg) * 32) + ((r & 7) * 4);
    *(uint4*)(meanF + base) = make_uint4(f2tf(acc.x * inv), f2tf(acc.y * inv),
                                         f2tf(acc.z * inv), f2tf(acc.w * inv));
}

// ---------------- layer-1 sage: mainloop + fp16 row-major + A-frag stores ----------
__global__ __launch_bounds__(256, 2) void sage_pipe_kernel(
    const float* __restrict__ meanF, const float* __restrict__ xF,
    const float* __restrict__ wlF, const float* __restrict__ wrF,
    const float* __restrict__ bl,
    __half* __restrict__ out_h, float* __restrict__ outF) {
    extern __shared__ float smem[];
    uint32_t sbase = smem_u32(smem);
    const int t = threadIdx.x;
    const int wid = t >> 5, lid = t & 31;
    const int bm = blockIdx.x;
    const int node0 = bm * 128;

    sage_mainloop(smem, sbase, meanF + (size_t)bm * SLAB, xF + (size_t)bm * SLAB,
                  wlF, wrF, bl, t, wid, lid);

    // fp16 row-major store (for next gather)
#pragma unroll
    for (int i = 0; i < 16; i++) {
        int idx = t + i * 256;
        int row = idx >> 5, c4 = (idx & 31) * 4;
        int node = node0 + row;
        if (node < N_NODES) {
            const float* p = &smem[row * 132 + c4];
            *(uint2*)(out_h + (size_t)node * C_DIM + c4) =
                pack_half4(p[0], p[1], p[2], p[3]);
        }
    }
    // A-frag tf32 store (for next GEMM)
    float* slab = outF + (size_t)bm * SLAB;
#pragma unroll
    for (int i = 0; i < 16; i++) {
        int w = (t + i * 256) * 4;
        int lane = w & 31, reg = (w >> 5) & 3, tile = (w >> 7) & 7, k8c = w >> 10;
        int row = tile * 16 + (reg & 1) * 8 + (lane >> 2);
        int kb = k8c * 8 + ((reg >> 1) & 1) * 4;
        float4 v = *(const float4*)&smem[row * 132 + kb];
        *(uint4*)(slab + w) = make_uint4(f2tf(v.x), f2tf(v.y), f2tf(v.z), f2tf(v.w));
    }
}

// ---------------- layer-2 sage + FUSED head: h2 never leaves the SM ----------------
// After the sage mainloop stages relu(h2) into smem [128][132], each warp computes
// a 16-row x 72-col head GEMM (logits cols 0-63 + value col 64) directly from smem
// A-operands (f2tf on the fly) and global frag-ordered headBF (L1-resident, 64KB).
__global__ __launch_bounds__(256, 2) void sage_head_pipe_kernel(
    const float* __restrict__ meanF, const float* __restrict__ hF,
    const float* __restrict__ wlF, const float* __restrict__ wrF,
    const float* __restrict__ bl,
    const float* __restrict__ headBF,
    const float* __restrict__ ba, const float* __restrict__ bc,
    float* __restrict__ out) {
    extern __shared__ float smem[];
    uint32_t sbase = smem_u32(smem);
    const int t = threadIdx.x;
    const int wid = t >> 5, lid = t & 31;
    const int bm = blockIdx.x;
    const int node0 = bm * 128;

    sage_mainloop(smem, sbase, meanF + (size_t)bm * SLAB, hF + (size_t)bm * SLAB,
                  wlF, wrF, bl, t, wid, lid);

    // ---- fused head GEMM: warp wid owns rows wid*16..wid*16+15 ----
    float hacc[9][4];
#pragma unroll
    for (int j = 0; j < 9; j++) {
        hacc[j][0] = 0.f; hacc[j][1] = 0.f; hacc[j][2] = 0.f; hacc[j][3] = 0.f;
    }
    const int arow = wid * 16 + (lid >> 2);
#pragma unroll 4
    for (int k8 = 0; k8 < 16; k8++) {
        uint32_t a[4];
#pragma unroll
        for (int r = 0; r < 4; r++) {
            int row = arow + (r & 1) * 8;
            int k = k8 * 8 + (r >> 1) * 4 + (lid & 3);
            a[r] = f2tf(smem[row * 132 + k]);   // conflict-free: banks 4*(lid>>2)+(lid&3)
        }
        const float* bbase = headBF + (size_t)(k8 >> 2) * 4096
                           + (((size_t)(k8 & 3) * 16) * 2) * 32 + lid;
#pragma unroll
        for (int j = 0; j < 9; j++) {
            uint32_t b0 = __float_as_uint(__ldg(bbase + j * 64));
            uint32_t b1 = __float_as_uint(__ldg(bbase + j * 64 + 32));
            mma_tf32(hacc[j][0], hacc[j][1], hacc[j][2], hacc[j][3],
                     a[0], a[1], a[2], a[3], b0, b1);
        }
    }

    // store: cols 0..63 logits + ba; col 64 value + bc; cols 65..71 discarded
#pragma unroll
    for (int j = 0; j < 9; j++) {
        int col = j * 8 + (lid & 3) * 2;
        int n0 = node0 + arow;
        int n1 = n0 + 8;
        if (col < 64) {
            float b0 = __ldg(&ba[col]), b1 = __ldg(&ba[col + 1]);
            if (n0 < N_NODES)
                *(float2*)(out + (size_t)n0 * OUT_CH + col) =
                    make_float2(hacc[j][0] + b0, hacc[j][1] + b1);
            if (n1 < N_NODES)
                *(float2*)(out + (size_t)n1 * OUT_CH + col) =
                    make_float2(hacc[j][2] + b0, hacc[j][3] + b1);
        } else if (col == 64) {
            float b0 = __ldg(&bc[0]);
            if (n0 < N_NODES)
                out[(size_t)N_NODES * OUT_CH + n0] = hacc[j][0] + b0;
            if (n1 < N_NODES)
                out[(size_t)N_NODES * OUT_CH + n1] = hacc[j][2] + b0;
        }
    }
}

// ---------------- launch (single stream, 5 launches, no allocations) ------
extern "C" void kernel_launch(void* const* d_in, const int* in_sizes, int n_in,
                              void* d_out, int out_size) {
    const float* x   = (const float*)d_in[0];
    const void*  ei  = d_in[1];
    const float* w1l = (const float*)d_in[2];
    const float* b1l = (const float*)d_in[3];
    const float* w1r = (const float*)d_in[4];
    const float* w2l = (const float*)d_in[5];
    const float* b2l = (const float*)d_in[6];
    const float* w2r = (const float*)d_in[7];
    const float* wa  = (const float*)d_in[8];
    const float* ba  = (const float*)d_in[9];
    const float* wc  = (const float*)d_in[10];
    const float* bc  = (const float*)d_in[11];
    float* out = (float*)d_out;

    float *meanF, *xF, *h1F, *w1lF, *w1rF, *w2lF, *w2rF, *headBF;
    __half *xH, *h1H;
    int *cursor, *csr;
    cudaGetSymbolAddress((void**)&xH,     g_xH);
    cudaGetSymbolAddress((void**)&h1H,    g_h1H);
    cudaGetSymbolAddress((void**)&meanF,  g_meanF);
    cudaGetSymbolAddress((void**)&xF,     g_xF);
    cudaGetSymbolAddress((void**)&h1F,    g_h1F);
    cudaGetSymbolAddress((void**)&w1lF,   g_w1lF);
    cudaGetSymbolAddress((void**)&w1rF,   g_w1rF);
    cudaGetSymbolAddress((void**)&w2lF,   g_w2lF);
    cudaGetSymbolAddress((void**)&w2rF,   g_w2rF);
    cudaGetSymbolAddress((void**)&headBF, g_headBF);
    cudaGetSymbolAddress((void**)&cursor, g_cursor);
    cudaGetSymbolAddress((void**)&csr,    g_csr);

    const int SAGE_SMEM = 128 * 132 * 4;  // 67584 >= 64KB pipeline needs
    cudaFuncSetAttribute(sage_pipe_kernel, cudaFuncAttributeMaxDynamicSharedMemorySize, SAGE_SMEM);
    cudaFuncSetAttribute(sage_head_pipe_kernel, cudaFuncAttributeMaxDynamicSharedMemorySize, SAGE_SMEM);

    // ---- all prep in one wide kernel (convertA | prepw | fill) ----
    prep_all_kernel<<<PB_FILL, 256>>>(x, ei, w1l, w1r, w2l, w2r, wa, wc,
                                      xF, xH, w1lF, w1rF, w2lF, w2rF, headBF,
                                      cursor, csr);

    const int gather_blocks = (N_NODES * 32) / 256;  // 5000

    // ---- layer 1 ----
    gather_kernel<<<gather_blocks, 256>>>(cursor, csr, xH, meanF, 0);
    sage_pipe_kernel<<<NBLK, 256, SAGE_SMEM>>>(meanF, xF, w1lF, w1rF, b1l, h1H, h1F);

    // ---- layer 2 + fused head (h2 never hits global memory) ----
    gather_kernel<<<gather_blocks, 256>>>(cursor, csr, h1H, meanF, 1);
    sage_head_pipe_kernel<<<NBLK, 256, SAGE_SMEM>>>(meanF, h1F, w2lF, w2rF, b2l,
                                                    headBF, ba, bc, out);
}

// round 16
// speedup vs baseline: 2.0247x; 1.3618x over previous
#include <cuda_runtime.h>
#include <cuda_fp16.h>
#include <cstdint>

#define N_NODES 40000
#define N_EDGES 640000
#define C_DIM   128
#define OUT_CH  64
#define BUCKET  64
#define NBLK    313          // ceil(40000/128)
// fp16 A/B frag slab: 128x128 fp16 = 8192 words = 2048 uint4 = 32KB

// prep_all block partition
#define PB_CONV 1252                     // NBLK*4 convertA blocks
#define PB_W    (PB_CONV + 40)           // 40 prepw blocks (5 x 2048 uint4 groups)
#define PB_FILL (PB_W + 2500)            // 2500 fill blocks

// ---------------- device scratch (no allocations allowed) ----------------
__device__ __half g_xH[N_NODES * C_DIM];    // fp16 row-major x (gather source)
__device__ __half g_h1H[N_NODES * C_DIM];   // fp16 row-major h1 (gather source)
__device__ uint4 g_meanF[NBLK * 2048];      // fp16 A-frag slabs
__device__ uint4 g_xF[NBLK * 2048];
__device__ uint4 g_h1F[NBLK * 2048];
__device__ uint4 g_w1lF[2048], g_w1rF[2048], g_w2lF[2048], g_w2rF[2048], g_headBF[2048];
__device__ int   g_cursor[N_NODES];   // zero-initialized; self-restored each run
__device__ int   g_csr[N_NODES * BUCKET];

// ---------------- helpers ----------------
__device__ __forceinline__ uint32_t h2u(float a, float b) {
    __half2 h = __floats2half2_rn(a, b);
    return *(uint32_t*)&h;
}
__device__ __forceinline__ uint4 pack8(float4 v0, float4 v1) {
    return make_uint4(h2u(v0.x, v0.y), h2u(v0.z, v0.w), h2u(v1.x, v1.y), h2u(v1.z, v1.w));
}
__device__ __forceinline__ uint32_t smem_u32(const void* p) {
    uint32_t a;
    asm("{ .reg .u64 t; cvta.to.shared.u64 t, %1; cvt.u32.u64 %0, t; }" : "=r"(a) : "l"(p));
    return a;
}
__device__ __forceinline__ void cp16(uint32_t dst, const void* src) {
    asm volatile("cp.async.ca.shared.global [%0], [%1], 16;" :: "r"(dst), "l"(src));
}
#define CP_COMMIT() asm volatile("cp.async.commit_group;" ::: "memory")
#define CP_WAIT1()  asm volatile("cp.async.wait_group 1;" ::: "memory")
#define CP_WAIT0()  asm volatile("cp.async.wait_group 0;" ::: "memory")

__device__ __forceinline__ uint2 pack_half4(float a, float b, float c, float d) {
    return make_uint2(h2u(a, b), h2u(c, d));
}

// m16n8k16 fp16 mma, fp32 accumulate
__device__ __forceinline__ void mma_f16(float& d0, float& d1, float& d2, float& d3,
                                        uint32_t a0, uint32_t a1, uint32_t a2, uint32_t a3,
                                        uint32_t b0, uint32_t b1) {
    asm volatile(
        "mma.sync.aligned.m16n8k16.row.col.f32.f16.f16.f32 "
        "{%0,%1,%2,%3}, {%4,%5,%6,%7}, {%8,%9}, {%0,%1,%2,%3};"
        : "+f"(d0), "+f"(d1), "+f"(d2), "+f"(d3)
        : "r"(a0), "r"(a1), "r"(a2), "r"(a3), "r"(b0), "r"(b1));
}

// mma over one staged 128x128x32 fp16 chunk; warp tile 64 nodes x 32 outs
// A chunk: [k16=2][m_tile=8][reg=4][lane=32] words; B: [k16=2][n_tile=16][reg=2][lane=32]
__device__ __forceinline__ void mma_chunk_f16(const uint32_t* sA, const uint32_t* sB,
                                              float acc[4][4][4], int wm, int wn, int lid) {
#pragma unroll
    for (int k16 = 0; k16 < 2; k16++) {
        uint32_t a[4][4], b[4][2];
#pragma unroll
        for (int i = 0; i < 4; i++) {
            uint32_t base = ((k16 * 8 + (wm * 4 + i)) * 4) * 32 + lid;
            a[i][0] = sA[base];      a[i][1] = sA[base + 32];
            a[i][2] = sA[base + 64]; a[i][3] = sA[base + 96];
        }
#pragma unroll
        for (int j = 0; j < 4; j++) {
            uint32_t base = ((k16 * 16 + (wn * 4 + j)) * 2) * 32 + lid;
            b[j][0] = sB[base]; b[j][1] = sB[base + 32];
        }
#pragma unroll
        for (int i = 0; i < 4; i++)
#pragma unroll
            for (int j = 0; j < 4; j++)
                mma_f16(acc[i][j][0], acc[i][j][1], acc[i][j][2], acc[i][j][3],
                        a[i][0], a[i][1], a[i][2], a[i][3], b[j][0], b[j][1]);
    }
}

// shared sage mainloop: relu([mean|x]@[wl;wr]^T + bl) for 128 nodes -> smem [128][132] fp32.
// Pipeline stage = 16KB (A 8KB + B 8KB), double buffered in smem[0..32KB).
__device__ __forceinline__ void sage_mainloop(
    float* smem, uint32_t sbase,
    const uint4* A0, const uint4* A1,
    const uint4* W0, const uint4* W1, const float* bl,
    int t, int wid, int lid) {
    const int wm = wid >> 2, wn = wid & 3;
    float acc[4][4][4];
#pragma unroll
    for (int i = 0; i < 4; i++)
#pragma unroll
        for (int j = 0; j < 4; j++) {
            acc[i][j][0] = 0.f; acc[i][j][1] = 0.f; acc[i][j][2] = 0.f; acc[i][j][3] = 0.f;
        }

    {
#pragma unroll
        for (int i = 0; i < 2; i++) {
            int o = t + i * 256;                      // 0..511 uint4
            cp16(sbase + o * 16, A0 + o);
            cp16(sbase + 8192 + o * 16, W0 + o);
        }
        CP_COMMIT();
    }

#pragma unroll 1
    for (int ch = 0; ch < 8; ch++) {
        if (ch < 7) {
            int nc = ch + 1;
            const uint4* A = ((nc < 4) ? A0 : A1) + (nc & 3) * 512;
            const uint4* B = ((nc < 4) ? W0 : W1) + (nc & 3) * 512;
            uint32_t d = sbase + (uint32_t)((nc & 1) * 16384);
#pragma unroll
            for (int i = 0; i < 2; i++) {
                int o = t + i * 256;
                cp16(d + o * 16, A + o);
                cp16(d + 8192 + o * 16, B + o);
            }
            CP_COMMIT();
            CP_WAIT1();
        } else {
            CP_WAIT0();
        }
        __syncthreads();
        const uint32_t* sA = (const uint32_t*)smem + (ch & 1) * 4096;
        const uint32_t* sB = sA + 2048;
        mma_chunk_f16(sA, sB, acc, wm, wn, lid);
        __syncthreads();
    }

    // stage relu(acc+bias) into smem [128][132]
    const int lrow = wm * 64 + (lid >> 2);
    const int cbase = wn * 32 + (lid & 3) * 2;
#pragma unroll
    for (int j = 0; j < 4; j++) {
        int col = cbase + j * 8;
        float b0 = __ldg(&bl[col]), b1 = __ldg(&bl[col + 1]);
#pragma unroll
        for (int i = 0; i < 4; i++) {
            int r0 = lrow + i * 16;
            smem[r0 * 132 + col]     = fmaxf(acc[i][j][0] + b0, 0.f);
            smem[r0 * 132 + col + 1] = fmaxf(acc[i][j][1] + b1, 0.f);
            smem[(r0 + 8) * 132 + col]     = fmaxf(acc[i][j][2] + b0, 0.f);
            smem[(r0 + 8) * 132 + col + 1] = fmaxf(acc[i][j][3] + b1, 0.f);
        }
    }
    __syncthreads();
}

// ================= fused prep: convertA + prepw + fill in ONE kernel =================
__global__ __launch_bounds__(256) void prep_all_kernel(
    const float* __restrict__ x, const void* __restrict__ ei,
    const float* __restrict__ w1l, const float* __restrict__ w1r,
    const float* __restrict__ w2l, const float* __restrict__ w2r,
    const float* __restrict__ wa, const float* __restrict__ wc,
    uint4* __restrict__ xF, __half* __restrict__ xH,
    uint4* __restrict__ w1lF, uint4* __restrict__ w1rF,
    uint4* __restrict__ w2lF, uint4* __restrict__ w2rF,
    uint4* __restrict__ headBF,
    int* __restrict__ cursor, int* __restrict__ csr) {
    const int b = blockIdx.x;
    const int t = threadIdx.x;

    if (b < PB_CONV) {
        // ---- convertA: x -> fp16 A-frag slab chunk + fp16 row copy ----
        __shared__ __align__(16) float s[128][36];
        const int bm = b >> 2;
        const int ch = b & 3;
        const int node0 = bm * 128;
        uint4* slab = xF + (size_t)bm * 2048;
#pragma unroll
        for (int i = 0; i < 4; i++) {
            int idx = t + i * 256;
            int row = idx >> 3, k4 = (idx & 7) * 4;
            int node = node0 + row;
            bool valid = (node < N_NODES);
            if (!valid) node = N_NODES - 1;
            float4 v = __ldg((const float4*)(x + (size_t)node * C_DIM + ch * 32 + k4));
            *(float4*)&s[row][k4] = v;
            if (valid)
                *(uint2*)(xH + (size_t)node * C_DIM + ch * 32 + k4) =
                    pack_half4(v.x, v.y, v.z, v.w);
        }
        __syncthreads();
#pragma unroll
        for (int i = 0; i < 2; i++) {
            int g2 = t + i * 256;            // 0..511 uint4 groups in this chunk
            int w = g2 * 4;
            int lane = w & 31, reg = (w >> 5) & 3, tile = (w >> 7) & 7, k16in = (w >> 10) & 1;
            int row = tile * 16 + (reg & 1) * 8 + (lane >> 2);
            int kl = k16in * 16 + ((reg >> 1) & 1) * 8;
            float4 v0 = *(const float4*)&s[row][kl];
            float4 v1 = *(const float4*)&s[row][kl + 4];
            slab[ch * 512 + g2] = pack8(v0, v1);
        }
    } else if (b < PB_W) {
        // ---- prepw: weights row-major fp32 -> fp16 B-frag ----
        int gid = (b - PB_CONV) * 256 + t;   // 0..10239
        int m = gid >> 11, g = gid & 2047;
        int w = g * 4;
        int lane = w & 31, reg = (w >> 5) & 1, ntile = (w >> 6) & 15, k16 = (w >> 10) & 7;
        int n = ntile * 8 + (lane >> 2);
        int k = k16 * 16 + reg * 8;
        float4 v0 = make_float4(0.f, 0.f, 0.f, 0.f);
        float4 v1 = make_float4(0.f, 0.f, 0.f, 0.f);
        uint4* dst;
        switch (m) {
            case 0: v0 = __ldg((const float4*)(w1l + (size_t)n * C_DIM + k));
                    v1 = __ldg((const float4*)(w1l + (size_t)n * C_DIM + k + 4));
                    dst = w1lF; break;
            case 1: v0 = __ldg((const float4*)(w1r + (size_t)n * C_DIM + k));
                    v1 = __ldg((const float4*)(w1r + (size_t)n * C_DIM + k + 4));
                    dst = w1rF; break;
            case 2: v0 = __ldg((const float4*)(w2l + (size_t)n * C_DIM + k));
                    v1 = __ldg((const float4*)(w2l + (size_t)n * C_DIM + k + 4));
                    dst = w2lF; break;
            case 3: v0 = __ldg((const float4*)(w2r + (size_t)n * C_DIM + k));
                    v1 = __ldg((const float4*)(w2r + (size_t)n * C_DIM + k + 4));
                    dst = w2rF; break;
            default:
                if (n < 64) {
                    v0 = __ldg((const float4*)(wa + (size_t)n * C_DIM + k));
                    v1 = __ldg((const float4*)(wa + (size_t)n * C_DIM + k + 4));
                } else if (n == 64) {
                    v0 = __ldg((const float4*)(wc + k));
                    v1 = __ldg((const float4*)(wc + k + 4));
                }
                dst = headBF; break;
        }
        dst[g] = pack8(v0, v1);
    } else {
        // ---- fill: bucketed CSR build, inline int64/int32 detection ----
        __shared__ int s_is64;
        {
            bool ok = true;
            if (t < 16) {
                int lo = ((const int*)ei)[2 * t];
                int hi = ((const int*)ei)[2 * t + 1];
                ok = (hi == 0) && ((unsigned)lo < (unsigned)N_NODES);
            }
            unsigned m = __ballot_sync(0xffffffffu, ok);
            if (t == 0) s_is64 = (m == 0xffffffffu) ? 1 : 0;
        }
        __syncthreads();
        int is64 = s_is64;
        int e = (b - PB_W) * 256 + t;        // 0..639999 exactly
        int src, dst;
        if (is64) {
            src = (int)((const long long*)ei)[e];
            dst = (int)((const long long*)ei)[N_EDGES + e];
        } else {
            src = ((const int*)ei)[e];
            dst = ((const int*)ei)[N_EDGES + e];
        }
        int pos = atomicAdd(&cursor[dst], 1);
        if (pos < BUCKET) csr[dst * BUCKET + pos] = src;
    }
}

// ---------------- mean aggregation: warp per node, MLP=8, pipelined index loads ----
// Writes fp16 A-frag words directly (lane L holds channels 4L..4L+3 of row r).
__global__ __launch_bounds__(256) void gather_kernel(int* __restrict__ cursor,
                                                     const int* __restrict__ csr,
                                                     const __half* __restrict__ xh,
                                                     uint4* __restrict__ meanF,
                                                     int zero_cursor) {
    int gt = blockIdx.x * blockDim.x + threadIdx.x;
    int n = gt >> 5;
    if (n >= N_NODES) return;
    int lane = gt & 31;
    const int4* bkt4 = (const int4*)(csr + n * BUCKET);   // 256B-aligned buckets
    int4 ia = __ldg(&bkt4[0]);
    int4 ib = __ldg(&bkt4[1]);
    int deg = __ldg(&cursor[n]);
    int e = (deg < BUCKET) ? deg : BUCKET;
    if (zero_cursor && lane == 0) cursor[n] = 0;
    float4 acc = make_float4(0.f, 0.f, 0.f, 0.f);
    int i = 0;
    for (; i + 8 <= e; i += 8) {
        int pa = (i >> 2) + 2, pb = (i >> 2) + 3;
        if (pa > 15) pa = 15;
        if (pb > 15) pb = 15;
        int4 na = __ldg(&bkt4[pa]);
        int4 nb = __ldg(&bkt4[pb]);
        uint2 u0 = __ldg((const uint2*)(xh + (size_t)ia.x * C_DIM) + lane);
        uint2 u1 = __ldg((const uint2*)(xh + (size_t)ia.y * C_DIM) + lane);
        uint2 u2 = __ldg((const uint2*)(xh + (size_t)ia.z * C_DIM) + lane);
        uint2 u3 = __ldg((const uint2*)(xh + (size_t)ia.w * C_DIM) + lane);
        uint2 u4 = __ldg((const uint2*)(xh + (size_t)ib.x * C_DIM) + lane);
        uint2 u5 = __ldg((const uint2*)(xh + (size_t)ib.y * C_DIM) + lane);
        uint2 u6 = __ldg((const uint2*)(xh + (size_t)ib.z * C_DIM) + lane);
        uint2 u7 = __ldg((const uint2*)(xh + (size_t)ib.w * C_DIM) + lane);
        float2 p;
        p = __half22float2(*(__half2*)&u0.x); acc.x += p.x; acc.y += p.y;
        p = __half22float2(*(__half2*)&u0.y); acc.z += p.x; acc.w += p.y;
        p = __half22float2(*(__half2*)&u1.x); acc.x += p.x; acc.y += p.y;
        p = __half22float2(*(__half2*)&u1.y); acc.z += p.x; acc.w += p.y;
        p = __half22float2(*(__half2*)&u2.x); acc.x += p.x; acc.y += p.y;
        p = __half22float2(*(__half2*)&u2.y); acc.z += p.x; acc.w += p.y;
        p = __half22float2(*(__half2*)&u3.x); acc.x += p.x; acc.y += p.y;
        p = __half22float2(*(__half2*)&u3.y); acc.z += p.x; acc.w += p.y;
        p = __half22float2(*(__half2*)&u4.x); acc.x += p.x; acc.y += p.y;
        p = __half22float2(*(__half2*)&u4.y); acc.z += p.x; acc.w += p.y;
        p = __half22float2(*(__half2*)&u5.x); acc.x += p.x; acc.y += p.y;
        p = __half22float2(*(__half2*)&u5.y); acc.z += p.x; acc.w += p.y;
        p = __half22float2(*(__half2*)&u6.x); acc.x += p.x; acc.y += p.y;
        p = __half22float2(*(__half2*)&u6.y); acc.z += p.x; acc.w += p.y;
        p = __half22float2(*(__half2*)&u7.x); acc.x += p.x; acc.y += p.y;
        p = __half22float2(*(__half2*)&u7.y); acc.z += p.x; acc.w += p.y;
        ia = na; ib = nb;
    }
    if (i + 4 <= e) {
        uint2 u0 = __ldg((const uint2*)(xh + (size_t)ia.x * C_DIM) + lane);
        uint2 u1 = __ldg((const uint2*)(xh + (size_t)ia.y * C_DIM) + lane);
        uint2 u2 = __ldg((const uint2*)(xh + (size_t)ia.z * C_DIM) + lane);
        uint2 u3 = __ldg((const uint2*)(xh + (size_t)ia.w * C_DIM) + lane);
        float2 p;
        p = __half22float2(*(__half2*)&u0.x); acc.x += p.x; acc.y += p.y;
        p = __half22float2(*(__half2*)&u0.y); acc.z += p.x; acc.w += p.y;
        p = __half22float2(*(__half2*)&u1.x); acc.x += p.x; acc.y += p.y;
        p = __half22float2(*(__half2*)&u1.y); acc.z += p.x; acc.w += p.y;
        p = __half22float2(*(__half2*)&u2.x); acc.x += p.x; acc.y += p.y;
        p = __half22float2(*(__half2*)&u2.y); acc.z += p.x; acc.w += p.y;
        p = __half22float2(*(__half2*)&u3.x); acc.x += p.x; acc.y += p.y;
        p = __half22float2(*(__half2*)&u3.y); acc.z += p.x; acc.w += p.y;
        ia = ib;
        i += 4;
    }
    {
        const int tail[4] = {ia.x, ia.y, ia.z, ia.w};
        int tcount = e - i;
#pragma unroll
        for (int j = 0; j < 3; j++) {
            if (j < tcount) {
                uint2 u0 = __ldg((const uint2*)(xh + (size_t)tail[j] * C_DIM) + lane);
                float2 p;
                p = __half22float2(*(__half2*)&u0.x); acc.x += p.x; acc.y += p.y;
                p = __half22float2(*(__half2*)&u0.y); acc.z += p.x; acc.w += p.y;
            }
        }
    }
    float inv = 1.0f / fmaxf((float)deg, 1.0f);
    // fp16 frag write: k16 = lane>>2, reg = (r>>3&1)|((lane>>1&1)<<1), 2 words (uint2)
    int bm = n >> 7, r = n & 127;
    int k16 = lane >> 2;
    int reg = ((r >> 3) & 1) | (((lane >> 1) & 1) << 1);
    int tile = (r >> 4) & 7;
    size_t word = (size_t)bm * 8192 + (((k16 * 8 + tile) * 4 + reg) * 32)
                + (r & 7) * 4 + (lane & 1) * 2;
    *(uint2*)((uint32_t*)meanF + word) =
        make_uint2(h2u(acc.x * inv, acc.y * inv), h2u(acc.z * inv, acc.w * inv));
}

// ---------------- layer-1 sage: mainloop + fp16 row-major + fp16 A-frag stores ------
__global__ __launch_bounds__(256, 2) void sage_pipe_kernel(
    const uint4* __restrict__ meanF, const uint4* __restrict__ xF,
    const uint4* __restrict__ wlF, const uint4* __restrict__ wrF,
    const float* __restrict__ bl,
    __half* __restrict__ out_h, uint4* __restrict__ outF) {
    extern __shared__ float smem[];
    uint32_t sbase = smem_u32(smem);
    const int t = threadIdx.x;
    const int wid = t >> 5, lid = t & 31;
    const int bm = blockIdx.x;
    const int node0 = bm * 128;

    sage_mainloop(smem, sbase, meanF + (size_t)bm * 2048, xF + (size_t)bm * 2048,
                  wlF, wrF, bl, t, wid, lid);

    // fp16 row-major store (for next gather)
#pragma unroll
    for (int i = 0; i < 16; i++) {
        int idx = t + i * 256;
        int row = idx >> 5, c4 = (idx & 31) * 4;
        int node = node0 + row;
        if (node < N_NODES) {
            const float* p = &smem[row * 132 + c4];
            *(uint2*)(out_h + (size_t)node * C_DIM + c4) =
                pack_half4(p[0], p[1], p[2], p[3]);
        }
    }
    // fp16 A-frag store (for next GEMM): 2048 uint4 groups, 8 per thread
    uint4* slab = outF + (size_t)bm * 2048;
#pragma unroll
    for (int i = 0; i < 8; i++) {
        int g = t + i * 256;
        int w = g * 4;
        int lane = w & 31, reg = (w >> 5) & 3, tile = (w >> 7) & 7, k16 = w >> 10;
        int row = tile * 16 + (reg & 1) * 8 + (lane >> 2);
        int kl = k16 * 16 + ((reg >> 1) & 1) * 8;
        float4 v0 = *(const float4*)&smem[row * 132 + kl];
        float4 v1 = *(const float4*)&smem[row * 132 + kl + 4];
        slab[g] = pack8(v0, v1);
    }
}

// ---------------- layer-2 sage + FUSED head (fp16 mma) ----------------
__global__ __launch_bounds__(256, 2) void sage_head_pipe_kernel(
    const uint4* __restrict__ meanF, const uint4* __restrict__ hF,
    const uint4* __restrict__ wlF, const uint4* __restrict__ wrF,
    const float* __restrict__ bl,
    const uint4* __restrict__ headBF,
    const float* __restrict__ ba, const float* __restrict__ bc,
    float* __restrict__ out) {
    extern __shared__ float smem[];
    uint32_t sbase = smem_u32(smem);
    const int t = threadIdx.x;
    const int wid = t >> 5, lid = t & 31;
    const int bm = blockIdx.x;
    const int node0 = bm * 128;

    sage_mainloop(smem, sbase, meanF + (size_t)bm * 2048, hF + (size_t)bm * 2048,
                  wlF, wrF, bl, t, wid, lid);

    // ---- fused head: warp wid owns rows wid*16..wid*16+15; 8 k16 x 9 n-tiles ----
    float hacc[9][4];
#pragma unroll
    for (int j = 0; j < 9; j++) {
        hacc[j][0] = 0.f; hacc[j][1] = 0.f; hacc[j][2] = 0.f; hacc[j][3] = 0.f;
    }
    const int arow = wid * 16 + (lid >> 2);
    const uint32_t* hbw = (const uint32_t*)headBF;
#pragma unroll 2
    for (int k16 = 0; k16 < 8; k16++) {
        int k = k16 * 16 + (lid & 3) * 2;
        float2 p0 = *(const float2*)&smem[arow * 132 + k];
        float2 p1 = *(const float2*)&smem[(arow + 8) * 132 + k];
        float2 p2 = *(const float2*)&smem[arow * 132 + k + 8];
        float2 p3 = *(const float2*)&smem[(arow + 8) * 132 + k + 8];
        uint32_t a0 = h2u(p0.x, p0.y), a1 = h2u(p1.x, p1.y);
        uint32_t a2 = h2u(p2.x, p2.y), a3 = h2u(p3.x, p3.y);
        const uint32_t* hb = hbw + (size_t)k16 * 1024 + lid;
#pragma unroll
        for (int j = 0; j < 9; j++) {
            uint32_t b0 = __ldg(hb + j * 64);
            uint32_t b1 = __ldg(hb + j * 64 + 32);
            mma_f16(hacc[j][0], hacc[j][1], hacc[j][2], hacc[j][3],
                    a0, a1, a2, a3, b0, b1);
        }
    }

    // store: cols 0..63 logits + ba; col 64 value + bc; cols 65..71 discarded
#pragma unroll
    for (int j = 0; j < 9; j++) {
        int col = j * 8 + (lid & 3) * 2;
        int n0 = node0 + arow;
        int n1 = n0 + 8;
        if (col < 64) {
            float b0 = __ldg(&ba[col]), b1 = __ldg(&ba[col + 1]);
            if (n0 < N_NODES)
                *(float2*)(out + (size_t)n0 * OUT_CH + col) =
                    make_float2(hacc[j][0] + b0, hacc[j][1] + b1);
            if (n1 < N_NODES)
                *(float2*)(out + (size_t)n1 * OUT_CH + col) =
                    make_float2(hacc[j][2] + b0, hacc[j][3] + b1);
        } else if (col == 64) {
            float b0 = __ldg(&bc[0]);
            if (n0 < N_NODES)
                out[(size_t)N_NODES * OUT_CH + n0] = hacc[j][0] + b0;
            if (n1 < N_NODES)
                out[(size_t)N_NODES * OUT_CH + n1] = hacc[j][2] + b0;
        }
    }
}

// ---------------- launch (single stream, 5 launches, no allocations) ------
extern "C" void kernel_launch(void* const* d_in, const int* in_sizes, int n_in,
                              void* d_out, int out_size) {
    const float* x   = (const float*)d_in[0];
    const void*  ei  = d_in[1];
    const float* w1l = (const float*)d_in[2];
    const float* b1l = (const float*)d_in[3];
    const float* w1r = (const float*)d_in[4];
    const float* w2l = (const float*)d_in[5];
    const float* b2l = (const float*)d_in[6];
    const float* w2r = (const float*)d_in[7];
    const float* wa  = (const float*)d_in[8];
    const float* ba  = (const float*)d_in[9];
    const float* wc  = (const float*)d_in[10];
    const float* bc  = (const float*)d_in[11];
    float* out = (float*)d_out;

    uint4 *meanF, *xF, *h1F, *w1lF, *w1rF, *w2lF, *w2rF, *headBF;
    __half *xH, *h1H;
    int *cursor, *csr;
    cudaGetSymbolAddress((void**)&xH,     g_xH);
    cudaGetSymbolAddress((void**)&h1H,    g_h1H);
    cudaGetSymbolAddress((void**)&meanF,  g_meanF);
    cudaGetSymbolAddress((void**)&xF,     g_xF);
    cudaGetSymbolAddress((void**)&h1F,    g_h1F);
    cudaGetSymbolAddress((void**)&w1lF,   g_w1lF);
    cudaGetSymbolAddress((void**)&w1rF,   g_w1rF);
    cudaGetSymbolAddress((void**)&w2lF,   g_w2lF);
    cudaGetSymbolAddress((void**)&w2rF,   g_w2rF);
    cudaGetSymbolAddress((void**)&headBF, g_headBF);
    cudaGetSymbolAddress((void**)&cursor, g_cursor);
    cudaGetSymbolAddress((void**)&csr,    g_csr);

    const int SAGE_SMEM = 128 * 132 * 4;  // 67584 B (pipeline needs only 32KB)
    cudaFuncSetAttribute(sage_pipe_kernel, cudaFuncAttributeMaxDynamicSharedMemorySize, SAGE_SMEM);
    cudaFuncSetAttribute(sage_head_pipe_kernel, cudaFuncAttributeMaxDynamicSharedMemorySize, SAGE_SMEM);

    // ---- all prep in one wide kernel (convertA | prepw | fill) ----
    prep_all_kernel<<<PB_FILL, 256>>>(x, ei, w1l, w1r, w2l, w2r, wa, wc,
                                      xF, xH, w1lF, w1rF, w2lF, w2rF, headBF,
                                      cursor, csr);

    const int gather_blocks = (N_NODES * 32) / 256;  // 5000

    // ---- layer 1 ----
    gather_kernel<<<gather_blocks, 256>>>(cursor, csr, xH, meanF, 0);
    sage_pipe_kernel<<<NBLK, 256, SAGE_SMEM>>>(meanF, xF, w1lF, w1rF, b1l, h1H, h1F);

    // ---- layer 2 + fused head ----
    gather_kernel<<<gather_blocks, 256>>>(cursor, csr, h1H, meanF, 1);
    sage_head_pipe_kernel<<<NBLK, 256, SAGE_SMEM>>>(meanF, h1F, w2lF, w2rF, b2l,
                                                    headBF, ba, bc, out);
}

// round 17
// speedup vs baseline: 2.0951x; 1.0348x over previous
#include <cuda_runtime.h>
#include <cuda_fp16.h>
#include <cstdint>

#define N_NODES 40000
#define N_EDGES 640000
#define C_DIM   128
#define OUT_CH  64
#define BUCKET  64
#define NBLK    313          // ceil(40000/128)
// fp16 A/B frag slab: 128x128 fp16 = 8192 words = 2048 uint4 = 32KB

// prep_all block partition
#define PB_CONV 1252                     // NBLK*4 convertA blocks
#define PB_W    (PB_CONV + 40)           // 40 prepw blocks (5 x 2048 uint4 groups)
#define PB_FILL (PB_W + 2500)            // 2500 fill blocks

// fp16 staging: [128][136] halves, row stride 272 B (17x16 -> uint4-aligned rows)
#define SROW 136
#define SAGE_SMEM_BYTES (128 * SROW * 2)  // 34816; pipeline needs 32768 (overlapped)

// ---------------- device scratch (no allocations allowed) ----------------
__device__ __half g_xH[N_NODES * C_DIM];    // fp16 row-major x (gather source)
__device__ __half g_h1H[N_NODES * C_DIM];   // fp16 row-major h1 (gather source)
__device__ uint4 g_meanF[NBLK * 2048];      // fp16 A-frag slabs
__device__ uint4 g_xF[NBLK * 2048];
__device__ uint4 g_h1F[NBLK * 2048];
__device__ uint4 g_w1lF[2048], g_w1rF[2048], g_w2lF[2048], g_w2rF[2048], g_headBF[2048];
__device__ int   g_cursor[N_NODES];   // zero-initialized; self-restored each run
__device__ int   g_csr[N_NODES * BUCKET];

// ---------------- helpers ----------------
__device__ __forceinline__ uint32_t h2u(float a, float b) {
    __half2 h = __floats2half2_rn(a, b);
    return *(uint32_t*)&h;
}
__device__ __forceinline__ uint4 pack8(float4 v0, float4 v1) {
    return make_uint4(h2u(v0.x, v0.y), h2u(v0.z, v0.w), h2u(v1.x, v1.y), h2u(v1.z, v1.w));
}
__device__ __forceinline__ uint32_t smem_u32(const void* p) {
    uint32_t a;
    asm("{ .reg .u64 t; cvta.to.shared.u64 t, %1; cvt.u32.u64 %0, t; }" : "=r"(a) : "l"(p));
    return a;
}
__device__ __forceinline__ void cp16(uint32_t dst, const void* src) {
    asm volatile("cp.async.ca.shared.global [%0], [%1], 16;" :: "r"(dst), "l"(src));
}
#define CP_COMMIT() asm volatile("cp.async.commit_group;" ::: "memory")
#define CP_WAIT1()  asm volatile("cp.async.wait_group 1;" ::: "memory")
#define CP_WAIT0()  asm volatile("cp.async.wait_group 0;" ::: "memory")

__device__ __forceinline__ uint2 pack_half4(float a, float b, float c, float d) {
    return make_uint2(h2u(a, b), h2u(c, d));
}

// m16n8k16 fp16 mma, fp32 accumulate
__device__ __forceinline__ void mma_f16(float& d0, float& d1, float& d2, float& d3,
                                        uint32_t a0, uint32_t a1, uint32_t a2, uint32_t a3,
                                        uint32_t b0, uint32_t b1) {
    asm volatile(
        "mma.sync.aligned.m16n8k16.row.col.f32.f16.f16.f32 "
        "{%0,%1,%2,%3}, {%4,%5,%6,%7}, {%8,%9}, {%0,%1,%2,%3};"
        : "+f"(d0), "+f"(d1), "+f"(d2), "+f"(d3)
        : "r"(a0), "r"(a1), "r"(a2), "r"(a3), "r"(b0), "r"(b1));
}

// mma over one staged 128x128x32 fp16 chunk; warp tile 64 nodes x 32 outs
__device__ __forceinline__ void mma_chunk_f16(const uint32_t* sA, const uint32_t* sB,
                                              float acc[4][4][4], int wm, int wn, int lid) {
#pragma unroll
    for (int k16 = 0; k16 < 2; k16++) {
        uint32_t a[4][4], b[4][2];
#pragma unroll
        for (int i = 0; i < 4; i++) {
            uint32_t base = ((k16 * 8 + (wm * 4 + i)) * 4) * 32 + lid;
            a[i][0] = sA[base];      a[i][1] = sA[base + 32];
            a[i][2] = sA[base + 64]; a[i][3] = sA[base + 96];
        }
#pragma unroll
        for (int j = 0; j < 4; j++) {
            uint32_t base = ((k16 * 16 + (wn * 4 + j)) * 2) * 32 + lid;
            b[j][0] = sB[base]; b[j][1] = sB[base + 32];
        }
#pragma unroll
        for (int i = 0; i < 4; i++)
#pragma unroll
            for (int j = 0; j < 4; j++)
                mma_f16(acc[i][j][0], acc[i][j][1], acc[i][j][2], acc[i][j][3],
                        a[i][0], a[i][1], a[i][2], a[i][3], b[j][0], b[j][1]);
    }
}

// shared sage mainloop: relu([mean|x]@[wl;wr]^T + bl) -> smem as fp16 [128][136].
__device__ __forceinline__ void sage_mainloop(
    uint32_t* smemw, uint32_t sbase,
    const uint4* A0, const uint4* A1,
    const uint4* W0, const uint4* W1, const float* bl,
    int t, int wid, int lid) {
    const int wm = wid >> 2, wn = wid & 3;
    float acc[4][4][4];
#pragma unroll
    for (int i = 0; i < 4; i++)
#pragma unroll
        for (int j = 0; j < 4; j++) {
            acc[i][j][0] = 0.f; acc[i][j][1] = 0.f; acc[i][j][2] = 0.f; acc[i][j][3] = 0.f;
        }

    {
#pragma unroll
        for (int i = 0; i < 2; i++) {
            int o = t + i * 256;                      // 0..511 uint4
            cp16(sbase + o * 16, A0 + o);
            cp16(sbase + 8192 + o * 16, W0 + o);
        }
        CP_COMMIT();
    }

#pragma unroll 1
    for (int ch = 0; ch < 8; ch++) {
        if (ch < 7) {
            int nc = ch + 1;
            const uint4* A = ((nc < 4) ? A0 : A1) + (nc & 3) * 512;
            const uint4* B = ((nc < 4) ? W0 : W1) + (nc & 3) * 512;
            uint32_t d = sbase + (uint32_t)((nc & 1) * 16384);
#pragma unroll
            for (int i = 0; i < 2; i++) {
                int o = t + i * 256;
                cp16(d + o * 16, A + o);
                cp16(d + 8192 + o * 16, B + o);
            }
            CP_COMMIT();
            CP_WAIT1();
        } else {
            CP_WAIT0();
        }
        __syncthreads();
        const uint32_t* sA = smemw + (ch & 1) * 4096;
        const uint32_t* sB = sA + 2048;
        mma_chunk_f16(sA, sB, acc, wm, wn, lid);
        __syncthreads();
    }

    // stage relu(acc+bias) into fp16 smem [128][136]: one packed u32 per col pair
    const int lrow = wm * 64 + (lid >> 2);
    const int cbase = wn * 32 + (lid & 3) * 2;
#pragma unroll
    for (int j = 0; j < 4; j++) {
        int col = cbase + j * 8;
        float b0 = __ldg(&bl[col]), b1 = __ldg(&bl[col + 1]);
#pragma unroll
        for (int i = 0; i < 4; i++) {
            int r0 = lrow + i * 16;
            smemw[(r0 * SROW + col) >> 1] =
                h2u(fmaxf(acc[i][j][0] + b0, 0.f), fmaxf(acc[i][j][1] + b1, 0.f));
            smemw[(((r0 + 8) * SROW) + col) >> 1] =
                h2u(fmaxf(acc[i][j][2] + b0, 0.f), fmaxf(acc[i][j][3] + b1, 0.f));
        }
    }
    __syncthreads();
}

// ================= fused prep: convertA + prepw + fill in ONE kernel =================
__global__ __launch_bounds__(256) void prep_all_kernel(
    const float* __restrict__ x, const void* __restrict__ ei,
    const float* __restrict__ w1l, const float* __restrict__ w1r,
    const float* __restrict__ w2l, const float* __restrict__ w2r,
    const float* __restrict__ wa, const float* __restrict__ wc,
    uint4* __restrict__ xF, __half* __restrict__ xH,
    uint4* __restrict__ w1lF, uint4* __restrict__ w1rF,
    uint4* __restrict__ w2lF, uint4* __restrict__ w2rF,
    uint4* __restrict__ headBF,
    int* __restrict__ cursor, int* __restrict__ csr) {
    const int b = blockIdx.x;
    const int t = threadIdx.x;

    if (b < PB_CONV) {
        __shared__ __align__(16) float s[128][36];
        const int bm = b >> 2;
        const int ch = b & 3;
        const int node0 = bm * 128;
        uint4* slab = xF + (size_t)bm * 2048;
#pragma unroll
        for (int i = 0; i < 4; i++) {
            int idx = t + i * 256;
            int row = idx >> 3, k4 = (idx & 7) * 4;
            int node = node0 + row;
            bool valid = (node < N_NODES);
            if (!valid) node = N_NODES - 1;
            float4 v = __ldg((const float4*)(x + (size_t)node * C_DIM + ch * 32 + k4));
            *(float4*)&s[row][k4] = v;
            if (valid)
                *(uint2*)(xH + (size_t)node * C_DIM + ch * 32 + k4) =
                    pack_half4(v.x, v.y, v.z, v.w);
        }
        __syncthreads();
#pragma unroll
        for (int i = 0; i < 2; i++) {
            int g2 = t + i * 256;
            int w = g2 * 4;
            int lane = w & 31, reg = (w >> 5) & 3, tile = (w >> 7) & 7, k16in = (w >> 10) & 1;
            int row = tile * 16 + (reg & 1) * 8 + (lane >> 2);
            int kl = k16in * 16 + ((reg >> 1) & 1) * 8;
            float4 v0 = *(const float4*)&s[row][kl];
            float4 v1 = *(const float4*)&s[row][kl + 4];
            slab[ch * 512 + g2] = pack8(v0, v1);
        }
    } else if (b < PB_W) {
        int gid = (b - PB_CONV) * 256 + t;   // 0..10239
        int m = gid >> 11, g = gid & 2047;
        int w = g * 4;
        int lane = w & 31, reg = (w >> 5) & 1, ntile = (w >> 6) & 15, k16 = (w >> 10) & 7;
        int n = ntile * 8 + (lane >> 2);
        int k = k16 * 16 + reg * 8;
        float4 v0 = make_float4(0.f, 0.f, 0.f, 0.f);
        float4 v1 = make_float4(0.f, 0.f, 0.f, 0.f);
        uint4* dst;
        switch (m) {
            case 0: v0 = __ldg((const float4*)(w1l + (size_t)n * C_DIM + k));
                    v1 = __ldg((const float4*)(w1l + (size_t)n * C_DIM + k + 4));
                    dst = w1lF; break;
            case 1: v0 = __ldg((const float4*)(w1r + (size_t)n * C_DIM + k));
                    v1 = __ldg((const float4*)(w1r + (size_t)n * C_DIM + k + 4));
                    dst = w1rF; break;
            case 2: v0 = __ldg((const float4*)(w2l + (size_t)n * C_DIM + k));
                    v1 = __ldg((const float4*)(w2l + (size_t)n * C_DIM + k + 4));
                    dst = w2lF; break;
            case 3: v0 = __ldg((const float4*)(w2r + (size_t)n * C_DIM + k));
                    v1 = __ldg((const float4*)(w2r + (size_t)n * C_DIM + k + 4));
                    dst = w2rF; break;
            default:
                if (n < 64) {
                    v0 = __ldg((const float4*)(wa + (size_t)n * C_DIM + k));
                    v1 = __ldg((const float4*)(wa + (size_t)n * C_DIM + k + 4));
                } else if (n == 64) {
                    v0 = __ldg((const float4*)(wc + k));
                    v1 = __ldg((const float4*)(wc + k + 4));
                }
                dst = headBF; break;
        }
        dst[g] = pack8(v0, v1);
    } else {
        __shared__ int s_is64;
        {
            bool ok = true;
            if (t < 16) {
                int lo = ((const int*)ei)[2 * t];
                int hi = ((const int*)ei)[2 * t + 1];
                ok = (hi == 0) && ((unsigned)lo < (unsigned)N_NODES);
            }
            unsigned m = __ballot_sync(0xffffffffu, ok);
            if (t == 0) s_is64 = (m == 0xffffffffu) ? 1 : 0;
        }
        __syncthreads();
        int is64 = s_is64;
        int e = (b - PB_W) * 256 + t;
        int src, dst;
        if (is64) {
            src = (int)((const long long*)ei)[e];
            dst = (int)((const long long*)ei)[N_EDGES + e];
        } else {
            src = ((const int*)ei)[e];
            dst = ((const int*)ei)[N_EDGES + e];
        }
        int pos = atomicAdd(&cursor[dst], 1);
        if (pos < BUCKET) csr[dst * BUCKET + pos] = src;
    }
}

// ---------------- mean aggregation: warp per node, MLP=8, pipelined index loads ----
__global__ __launch_bounds__(256) void gather_kernel(int* __restrict__ cursor,
                                                     const int* __restrict__ csr,
                                                     const __half* __restrict__ xh,
                                                     uint4* __restrict__ meanF,
                                                     int zero_cursor) {
    int gt = blockIdx.x * blockDim.x + threadIdx.x;
    int n = gt >> 5;
    if (n >= N_NODES) return;
    int lane = gt & 31;
    const int4* bkt4 = (const int4*)(csr + n * BUCKET);
    int4 ia = __ldg(&bkt4[0]);
    int4 ib = __ldg(&bkt4[1]);
    int deg = __ldg(&cursor[n]);
    int e = (deg < BUCKET) ? deg : BUCKET;
    if (zero_cursor && lane == 0) cursor[n] = 0;
    float4 acc = make_float4(0.f, 0.f, 0.f, 0.f);
    int i = 0;
    for (; i + 8 <= e; i += 8) {
        int pa = (i >> 2) + 2, pb = (i >> 2) + 3;
        if (pa > 15) pa = 15;
        if (pb > 15) pb = 15;
        int4 na = __ldg(&bkt4[pa]);
        int4 nb = __ldg(&bkt4[pb]);
        uint2 u0 = __ldg((const uint2*)(xh + (size_t)ia.x * C_DIM) + lane);
        uint2 u1 = __ldg((const uint2*)(xh + (size_t)ia.y * C_DIM) + lane);
        uint2 u2 = __ldg((const uint2*)(xh + (size_t)ia.z * C_DIM) + lane);
        uint2 u3 = __ldg((const uint2*)(xh + (size_t)ia.w * C_DIM) + lane);
        uint2 u4 = __ldg((const uint2*)(xh + (size_t)ib.x * C_DIM) + lane);
        uint2 u5 = __ldg((const uint2*)(xh + (size_t)ib.y * C_DIM) + lane);
        uint2 u6 = __ldg((const uint2*)(xh + (size_t)ib.z * C_DIM) + lane);
        uint2 u7 = __ldg((const uint2*)(xh + (size_t)ib.w * C_DIM) + lane);
        float2 p;
        p = __half22float2(*(__half2*)&u0.x); acc.x += p.x; acc.y += p.y;
        p = __half22float2(*(__half2*)&u0.y); acc.z += p.x; acc.w += p.y;
        p = __half22float2(*(__half2*)&u1.x); acc.x += p.x; acc.y += p.y;
        p = __half22float2(*(__half2*)&u1.y); acc.z += p.x; acc.w += p.y;
        p = __half22float2(*(__half2*)&u2.x); acc.x += p.x; acc.y += p.y;
        p = __half22float2(*(__half2*)&u2.y); acc.z += p.x; acc.w += p.y;
        p = __half22float2(*(__half2*)&u3.x); acc.x += p.x; acc.y += p.y;
        p = __half22float2(*(__half2*)&u3.y); acc.z += p.x; acc.w += p.y;
        p = __half22float2(*(__half2*)&u4.x); acc.x += p.x; acc.y += p.y;
        p = __half22float2(*(__half2*)&u4.y); acc.z += p.x; acc.w += p.y;
        p = __half22float2(*(__half2*)&u5.x); acc.x += p.x; acc.y += p.y;
        p = __half22float2(*(__half2*)&u5.y); acc.z += p.x; acc.w += p.y;
        p = __half22float2(*(__half2*)&u6.x); acc.x += p.x; acc.y += p.y;
        p = __half22float2(*(__half2*)&u6.y); acc.z += p.x; acc.w += p.y;
        p = __half22float2(*(__half2*)&u7.x); acc.x += p.x; acc.y += p.y;
        p = __half22float2(*(__half2*)&u7.y); acc.z += p.x; acc.w += p.y;
        ia = na; ib = nb;
    }
    if (i + 4 <= e) {
        uint2 u0 = __ldg((const uint2*)(xh + (size_t)ia.x * C_DIM) + lane);
        uint2 u1 = __ldg((const uint2*)(xh + (size_t)ia.y * C_DIM) + lane);
        uint2 u2 = __ldg((const uint2*)(xh + (size_t)ia.z * C_DIM) + lane);
        uint2 u3 = __ldg((const uint2*)(xh + (size_t)ia.w * C_DIM) + lane);
        float2 p;
        p = __half22float2(*(__half2*)&u0.x); acc.x += p.x; acc.y += p.y;
        p = __half22float2(*(__half2*)&u0.y); acc.z += p.x; acc.w += p.y;
        p = __half22float2(*(__half2*)&u1.x); acc.x += p.x; acc.y += p.y;
        p = __half22float2(*(__half2*)&u1.y); acc.z += p.x; acc.w += p.y;
        p = __half22float2(*(__half2*)&u2.x); acc.x += p.x; acc.y += p.y;
        p = __half22float2(*(__half2*)&u2.y); acc.z += p.x; acc.w += p.y;
        p = __half22float2(*(__half2*)&u3.x); acc.x += p.x; acc.y += p.y;
        p = __half22float2(*(__half2*)&u3.y); acc.z += p.x; acc.w += p.y;
        ia = ib;
        i += 4;
    }
    {
        const int tail[4] = {ia.x, ia.y, ia.z, ia.w};
        int tcount = e - i;
#pragma unroll
        for (int j = 0; j < 3; j++) {
            if (j < tcount) {
                uint2 u0 = __ldg((const uint2*)(xh + (size_t)tail[j] * C_DIM) + lane);
                float2 p;
                p = __half22float2(*(__half2*)&u0.x); acc.x += p.x; acc.y += p.y;
                p = __half22float2(*(__half2*)&u0.y); acc.z += p.x; acc.w += p.y;
            }
        }
    }
    float inv = 1.0f / fmaxf((float)deg, 1.0f);
    int bm = n >> 7, r = n & 127;
    int k16 = lane >> 2;
    int reg = ((r >> 3) & 1) | (((lane >> 1) & 1) << 1);
    int tile = (r >> 4) & 7;
    size_t word = (size_t)bm * 8192 + (((k16 * 8 + tile) * 4 + reg) * 32)
                + (r & 7) * 4 + (lane & 1) * 2;
    *(uint2*)((uint32_t*)meanF + word) =
        make_uint2(h2u(acc.x * inv, acc.y * inv), h2u(acc.z * inv, acc.w * inv));
}

// ---------------- layer-1 sage: mainloop + fp16 row-major + fp16 A-frag stores ------
__global__ __launch_bounds__(256, 2) void sage_pipe_kernel(
    const uint4* __restrict__ meanF, const uint4* __restrict__ xF,
    const uint4* __restrict__ wlF, const uint4* __restrict__ wrF,
    const float* __restrict__ bl,
    __half* __restrict__ out_h, uint4* __restrict__ outF) {
    extern __shared__ __align__(16) uint32_t smemw[];
    uint32_t sbase = smem_u32(smemw);
    const int t = threadIdx.x;
    const int wid = t >> 5, lid = t & 31;
    const int bm = blockIdx.x;
    const int node0 = bm * 128;

    sage_mainloop(smemw, sbase, meanF + (size_t)bm * 2048, xF + (size_t)bm * 2048,
                  wlF, wrF, bl, t, wid, lid);

    const __half* sh = (const __half*)smemw;
    // fp16 row-major store: pure uint2 copies (4 halves each)
#pragma unroll
    for (int i = 0; i < 16; i++) {
        int idx = t + i * 256;                 // 0..4095; 32 chunks of 4 halves per row
        int row = idx >> 5, c4 = (idx & 31) * 4;
        int node = node0 + row;
        if (node < N_NODES)
            *(uint2*)(out_h + (size_t)node * C_DIM + c4) =
                *(const uint2*)(sh + row * SROW + c4);
    }
    // fp16 A-frag store: pure uint4 copies (8 halves each)
    uint4* slab = outF + (size_t)bm * 2048;
#pragma unroll
    for (int i = 0; i < 8; i++) {
        int g = t + i * 256;
        int w = g * 4;
        int lane = w & 31, reg = (w >> 5) & 3, tile = (w >> 7) & 7, k16 = w >> 10;
        int row = tile * 16 + (reg & 1) * 8 + (lane >> 2);
        int kl = k16 * 16 + ((reg >> 1) & 1) * 8;
        slab[g] = *(const uint4*)(sh + row * SROW + kl);
    }
}

// ---------------- layer-2 sage + FUSED head (A-ops read directly from fp16 smem) ----
__global__ __launch_bounds__(256, 2) void sage_head_pipe_kernel(
    const uint4* __restrict__ meanF, const uint4* __restrict__ hF,
    const uint4* __restrict__ wlF, const uint4* __restrict__ wrF,
    const float* __restrict__ bl,
    const uint4* __restrict__ headBF,
    const float* __restrict__ ba, const float* __restrict__ bc,
    float* __restrict__ out) {
    extern __shared__ __align__(16) uint32_t smemw[];
    uint32_t sbase = smem_u32(smemw);
    const int t = threadIdx.x;
    const int wid = t >> 5, lid = t & 31;
    const int bm = blockIdx.x;
    const int node0 = bm * 128;

    sage_mainloop(smemw, sbase, meanF + (size_t)bm * 2048, hF + (size_t)bm * 2048,
                  wlF, wrF, bl, t, wid, lid);

    // ---- fused head: A-operand = staged fp16 word, bare LDS.32 ----
    float hacc[9][4];
#pragma unroll
    for (int j = 0; j < 9; j++) {
        hacc[j][0] = 0.f; hacc[j][1] = 0.f; hacc[j][2] = 0.f; hacc[j][3] = 0.f;
    }
    const int arow = wid * 16 + (lid >> 2);
    const uint32_t base32 = (uint32_t)arow * (SROW / 2) + (lid & 3);  // u32 index
    const uint32_t* hbw = (const uint32_t*)headBF;
#pragma unroll 2
    for (int k16 = 0; k16 < 8; k16++) {
        uint32_t a0 = smemw[base32 + k16 * 8];
        uint32_t a1 = smemw[base32 + k16 * 8 + 8 * (SROW / 2)];
        uint32_t a2 = smemw[base32 + k16 * 8 + 4];
        uint32_t a3 = smemw[base32 + k16 * 8 + 4 + 8 * (SROW / 2)];
        const uint32_t* hb = hbw + (size_t)k16 * 1024 + lid;
#pragma unroll
        for (int j = 0; j < 9; j++) {
            uint32_t b0 = __ldg(hb + j * 64);
            uint32_t b1 = __ldg(hb + j * 64 + 32);
            mma_f16(hacc[j][0], hacc[j][1], hacc[j][2], hacc[j][3],
                    a0, a1, a2, a3, b0, b1);
        }
    }

#pragma unroll
    for (int j = 0; j < 9; j++) {
        int col = j * 8 + (lid & 3) * 2;
        int n0 = node0 + arow;
        int n1 = n0 + 8;
        if (col < 64) {
            float b0 = __ldg(&ba[col]), b1 = __ldg(&ba[col + 1]);
            if (n0 < N_NODES)
                *(float2*)(out + (size_t)n0 * OUT_CH + col) =
                    make_float2(hacc[j][0] + b0, hacc[j][1] + b1);
            if (n1 < N_NODES)
                *(float2*)(out + (size_t)n1 * OUT_CH + col) =
                    make_float2(hacc[j][2] + b0, hacc[j][3] + b1);
        } else if (col == 64) {
            float b0 = __ldg(&bc[0]);
            if (n0 < N_NODES)
                out[(size_t)N_NODES * OUT_CH + n0] = hacc[j][0] + b0;
            if (n1 < N_NODES)
                out[(size_t)N_NODES * OUT_CH + n1] = hacc[j][2] + b0;
        }
    }
}

// ---------------- launch (single stream, 5 launches, no allocations) ------
extern "C" void kernel_launch(void* const* d_in, const int* in_sizes, int n_in,
                              void* d_out, int out_size) {
    const float* x   = (const float*)d_in[0];
    const void*  ei  = d_in[1];
    const float* w1l = (const float*)d_in[2];
    const float* b1l = (const float*)d_in[3];
    const float* w1r = (const float*)d_in[4];
    const float* w2l = (const float*)d_in[5];
    const float* b2l = (const float*)d_in[6];
    const float* w2r = (const float*)d_in[7];
    const float* wa  = (const float*)d_in[8];
    const float* ba  = (const float*)d_in[9];
    const float* wc  = (const float*)d_in[10];
    const float* bc  = (const float*)d_in[11];
    float* out = (float*)d_out;

    uint4 *meanF, *xF, *h1F, *w1lF, *w1rF, *w2lF, *w2rF, *headBF;
    __half *xH, *h1H;
    int *cursor, *csr;
    cudaGetSymbolAddress((void**)&xH,     g_xH);
    cudaGetSymbolAddress((void**)&h1H,    g_h1H);
    cudaGetSymbolAddress((void**)&meanF,  g_meanF);
    cudaGetSymbolAddress((void**)&xF,     g_xF);
    cudaGetSymbolAddress((void**)&h1F,    g_h1F);
    cudaGetSymbolAddress((void**)&w1lF,   g_w1lF);
    cudaGetSymbolAddress((void**)&w1rF,   g_w1rF);
    cudaGetSymbolAddress((void**)&w2lF,   g_w2lF);
    cudaGetSymbolAddress((void**)&w2rF,   g_w2rF);
    cudaGetSymbolAddress((void**)&headBF, g_headBF);
    cudaGetSymbolAddress((void**)&cursor, g_cursor);
    cudaGetSymbolAddress((void**)&csr,    g_csr);

    cudaFuncSetAttribute(sage_pipe_kernel, cudaFuncAttributeMaxDynamicSharedMemorySize,
                         SAGE_SMEM_BYTES);
    cudaFuncSetAttribute(sage_head_pipe_kernel, cudaFuncAttributeMaxDynamicSharedMemorySize,
                         SAGE_SMEM_BYTES);

    // ---- all prep in one wide kernel (convertA | prepw | fill) ----
    prep_all_kernel<<<PB_FILL, 256>>>(x, ei, w1l, w1r, w2l, w2r, wa, wc,
                                      xF, xH, w1lF, w1rF, w2lF, w2rF, headBF,
                                      cursor, csr);

    const int gather_blocks = (N_NODES * 32) / 256;  // 5000

    // ---- layer 1 ----
    gather_kernel<<<gather_blocks, 256>>>(cursor, csr, xH, meanF, 0);
    sage_pipe_kernel<<<NBLK, 256, SAGE_SMEM_BYTES>>>(meanF, xF, w1lF, w1rF, b1l, h1H, h1F);

    // ---- layer 2 + fused head ----
    gather_kernel<<<gather_blocks, 256>>>(cursor, csr, h1H, meanF, 1);
    sage_head_pipe_kernel<<<NBLK, 256, SAGE_SMEM_BYTES>>>(meanF, h1F, w2lF, w2rF, b2l,
                                                          headBF, ba, bc, out);
}